// round 1
// baseline (speedup 1.0000x reference)
#include <cuda_runtime.h>
#include <math.h>

#define NN 50000
#define HH 128
#define TT 4
#define EE 150000
#define NE (TT*EE)
#define G3H (3*HH)   // 384

// ---------------- scratch (device globals; no allocation allowed) ----------
__device__ float    g_M[(size_t)TT*NN*HH];   // per-type transformed node features
__device__ float    g_inc[(size_t)NN*HH];    // incoming messages
__device__ float    g_gx[(size_t)NN*G3H];
__device__ float    g_gh[(size_t)NN*G3H];
__device__ float    g_h[(size_t)NN*HH];
__device__ int      g_cnt[NN];
__device__ int      g_off[NN+1];
__device__ int      g_pos[NN];
__device__ unsigned g_ent[NE];               // (type<<16) | src

// ---------------- CSR build ----------------
__global__ void hist_kernel(const int* __restrict__ edges) {
    int i = blockIdx.x * blockDim.x + threadIdx.x;
    if (i < NE) atomicAdd(&g_cnt[edges[2*i+1]], 1);
}

__global__ void scan_kernel() {
    __shared__ int s[1024];
    __shared__ int carry;
    if (threadIdx.x == 0) carry = 0;
    __syncthreads();
    for (int base = 0; base < NN; base += 1024) {
        int i = base + threadIdx.x;
        int v = (i < NN) ? g_cnt[i] : 0;
        s[threadIdx.x] = v;
        __syncthreads();
        #pragma unroll
        for (int off = 1; off < 1024; off <<= 1) {
            int t = (threadIdx.x >= off) ? s[threadIdx.x - off] : 0;
            __syncthreads();
            s[threadIdx.x] += t;
            __syncthreads();
        }
        int excl = carry + s[threadIdx.x] - v;
        if (i < NN) { g_off[i] = excl; g_pos[i] = excl; }
        __syncthreads();
        if (threadIdx.x == 1023) carry += s[1023];
        __syncthreads();
    }
    if (threadIdx.x == 0) g_off[NN] = carry;
}

__global__ void fill_kernel(const int* __restrict__ edges) {
    int i = blockIdx.x * blockDim.x + threadIdx.x;
    if (i < NE) {
        int t   = i / EE;
        int src = edges[2*i];
        int tgt = edges[2*i+1];
        int p = atomicAdd(&g_pos[tgt], 1);
        g_ent[p] = ((unsigned)t << 16) | (unsigned)src;
    }
}

// ---------------- message gather (atomic-free segment sum) ----------------
__global__ void gather_kernel(const float* __restrict__ b /* msg_b + l*T*H */) {
    int gw   = (blockIdx.x * blockDim.x + threadIdx.x) >> 5;
    int lane = threadIdx.x & 31;
    if (gw >= NN) return;
    int s = g_off[gw], e = g_off[gw+1];
    float4 acc = make_float4(0.f, 0.f, 0.f, 0.f);
    for (int i = s; i < e; i++) {
        unsigned ent = g_ent[i];
        int t   = (int)(ent >> 16);
        int src = (int)(ent & 0xFFFFu);
        float4 mv = *(const float4*)(g_M + ((size_t)t*NN + src)*HH + lane*4);
        float4 bv = *(const float4*)(b + t*HH + lane*4);
        acc.x += mv.x + bv.x;
        acc.y += mv.y + bv.y;
        acc.z += mv.z + bv.z;
        acc.w += mv.w + bv.w;
    }
    *(float4*)(g_inc + (size_t)gw*HH + lane*4) = acc;
}

// ---------------- generic GEMM: C = [A0|A1] @ W^T (+bias) ----------------
// A0/A1: [NN][128] fp32 (A1 optional second K-chunk). W: row-major [NoutTot][ldW].
// Block computes 64 rows x 128 cols. blockIdx.y selects either a column block
// (colmult=128) or a separate W/C instance via strides (Wystride/Cystride).
__global__ void __launch_bounds__(256)
gemm_kernel(const float* __restrict__ A0, const float* __restrict__ A1,
            const float* __restrict__ W, int ldW, long long Wystride,
            const float* __restrict__ bias,
            float* __restrict__ C, int ldC, long long Cystride, int colmult)
{
    extern __shared__ float smem[];
    float* As = smem;              // [64][132] padded
    float* Ws = smem + 64*132;     // [128][128], layout Ws[k][f]

    int tid = threadIdx.x;
    int tx = tid & 15, ty = tid >> 4;
    int cb = blockIdx.y * colmult;
    W += (long long)blockIdx.y * Wystride;
    C += (long long)blockIdx.y * Cystride;
    int row_base = blockIdx.x * 64;

    float acc[4][8];
    #pragma unroll
    for (int i = 0; i < 4; i++)
        #pragma unroll
        for (int j = 0; j < 8; j++) acc[i][j] = 0.f;

    int nchunks = (A1 != nullptr) ? 2 : 1;
    for (int ch = 0; ch < nchunks; ch++) {
        const float* A = ch ? A1 : A0;
        // load A tile: 64x128, coalesced float4
        #pragma unroll
        for (int it = 0; it < 8; it++) {
            int idx = tid + it*256;
            int r = idx >> 5, c4 = idx & 31;
            int grow = row_base + r;
            float4 v = make_float4(0.f,0.f,0.f,0.f);
            if (grow < NN) v = *(const float4*)(A + (size_t)grow*HH + c4*4);
            *(float4*)(As + r*132 + c4*4) = v;
        }
        // load W chunk transposed into Ws[k][f]; smem stores conflict-free
        #pragma unroll
        for (int it = 0; it < 16; it++) {
            int idx = tid + it*256;
            int f = idx & 127, k4 = idx >> 7;
            float4 w = *(const float4*)(W + (size_t)(cb + f)*ldW + ch*128 + k4*4);
            Ws[(k4*4+0)*128 + f] = w.x;
            Ws[(k4*4+1)*128 + f] = w.y;
            Ws[(k4*4+2)*128 + f] = w.z;
            Ws[(k4*4+3)*128 + f] = w.w;
        }
        __syncthreads();
        #pragma unroll 8
        for (int k = 0; k < 128; k++) {
            float4 b0 = *(float4*)(Ws + k*128 + tx*8);
            float4 b1 = *(float4*)(Ws + k*128 + tx*8 + 4);
            #pragma unroll
            for (int i = 0; i < 4; i++) {
                float a = As[(ty*4+i)*132 + k];
                acc[i][0] += a*b0.x; acc[i][1] += a*b0.y;
                acc[i][2] += a*b0.z; acc[i][3] += a*b0.w;
                acc[i][4] += a*b1.x; acc[i][5] += a*b1.y;
                acc[i][6] += a*b1.z; acc[i][7] += a*b1.w;
            }
        }
        __syncthreads();
    }

    float4 bv0 = make_float4(0.f,0.f,0.f,0.f), bv1 = bv0;
    if (bias) {
        bv0 = *(const float4*)(bias + cb + tx*8);
        bv1 = *(const float4*)(bias + cb + tx*8 + 4);
    }
    #pragma unroll
    for (int i = 0; i < 4; i++) {
        int grow = row_base + ty*4 + i;
        if (grow < NN) {
            float4 o0 = make_float4(acc[i][0]+bv0.x, acc[i][1]+bv0.y,
                                    acc[i][2]+bv0.z, acc[i][3]+bv0.w);
            float4 o1 = make_float4(acc[i][4]+bv1.x, acc[i][5]+bv1.y,
                                    acc[i][6]+bv1.z, acc[i][7]+bv1.w);
            *(float4*)(C + (size_t)grow*ldC + cb + tx*8)     = o0;
            *(float4*)(C + (size_t)grow*ldC + cb + tx*8 + 4) = o1;
        }
    }
}

// ---------------- fused GRU gate ----------------
__global__ void gate_kernel(const float* __restrict__ h, float* __restrict__ hout) {
    int idx = blockIdx.x * blockDim.x + threadIdx.x;
    if (idx >= NN*HH) return;
    int n = idx >> 7, f = idx & 127;
    const float* gx = g_gx + (size_t)n*G3H;
    const float* gh = g_gh + (size_t)n*G3H;
    float xr = gx[f], xz = gx[HH+f], xn = gx[2*HH+f];
    float hr = gh[f], hz = gh[HH+f], hn = gh[2*HH+f];
    float r = 1.f / (1.f + expf(-(xr + hr)));
    float z = 1.f / (1.f + expf(-(xz + hz)));
    float nv = tanhf(xn + r*hn);
    hout[idx] = (1.f - z)*nv + z*h[idx];
}

// ---------------- launch ----------------
extern "C" void kernel_launch(void* const* d_in, const int* in_sizes, int n_in,
                              void* d_out, int out_size) {
    const float* x      = (const float*)d_in[0];
    const int*   edges  = (const int*)  d_in[1];
    const float* msg_W  = (const float*)d_in[2];
    const float* msg_b  = (const float*)d_in[3];
    const float* g0_Wih = (const float*)d_in[4];
    const float* g0_Whh = (const float*)d_in[5];
    const float* g0_bih = (const float*)d_in[6];
    const float* g0_bhh = (const float*)d_in[7];
    const float* g1_Wih = (const float*)d_in[8];
    const float* g1_Whh = (const float*)d_in[9];
    const float* g1_bih = (const float*)d_in[10];
    const float* g1_bhh = (const float*)d_in[11];

    float *pM, *pInc, *pGx, *pGh, *pH; int *pCnt;
    cudaGetSymbolAddress((void**)&pM,   g_M);
    cudaGetSymbolAddress((void**)&pInc, g_inc);
    cudaGetSymbolAddress((void**)&pGx,  g_gx);
    cudaGetSymbolAddress((void**)&pGh,  g_gh);
    cudaGetSymbolAddress((void**)&pH,   g_h);
    cudaGetSymbolAddress((void**)&pCnt, g_cnt);

    size_t smem = (64*132 + 128*128) * sizeof(float);   // 99328 B
    cudaFuncSetAttribute(gemm_kernel,
                         cudaFuncAttributeMaxDynamicSharedMemorySize, (int)smem);

    // CSR build (once per launch, reused by all 6 timesteps)
    cudaMemsetAsync(pCnt, 0, NN*sizeof(int), 0);
    hist_kernel<<<(NE+255)/256, 256>>>(edges);
    scan_kernel<<<1, 1024>>>();
    fill_kernel<<<(NE+255)/256, 256>>>(edges);

    // h = x
    cudaMemcpyAsync(pH, x, (size_t)NN*HH*sizeof(float),
                    cudaMemcpyDeviceToDevice, 0);

    const int GX = (NN + 63) / 64;   // 782
    for (int l = 0; l < 2; l++) {
        for (int s = 0; s < 3; s++) {
            // per-type node transform: M[t] = h @ W[l][t]^T
            gemm_kernel<<<dim3(GX, TT), 256, smem>>>(
                pH, nullptr,
                msg_W + (size_t)l*TT*HH*HH, HH, (long long)HH*HH,
                nullptr,
                pM, HH, (long long)NN*HH, 0);
            // inc = segment_sum(M[t][src] + b[t])
            gather_kernel<<<(NN*32)/256, 256>>>(msg_b + (size_t)l*TT*HH);
            // GRU input/hidden GEMMs
            if (l == 0) {
                gemm_kernel<<<dim3(GX, 3), 256, smem>>>(
                    pInc, nullptr, g0_Wih, HH, 0LL, g0_bih, pGx, G3H, 0LL, 128);
                gemm_kernel<<<dim3(GX, 3), 256, smem>>>(
                    pH, nullptr, g0_Whh, HH, 0LL, g0_bhh, pGh, G3H, 0LL, 128);
            } else {
                gemm_kernel<<<dim3(GX, 3), 256, smem>>>(
                    x, pInc, g1_Wih, 2*HH, 0LL, g1_bih, pGx, G3H, 0LL, 128);
                gemm_kernel<<<dim3(GX, 3), 256, smem>>>(
                    pH, nullptr, g1_Whh, HH, 0LL, g1_bhh, pGh, G3H, 0LL, 128);
            }
            bool last = (l == 1 && s == 2);
            gate_kernel<<<(NN*HH+255)/256, 256>>>(pH, last ? (float*)d_out : pH);
        }
    }
}

// round 3
// speedup vs baseline: 2.9554x; 2.9554x over previous
#include <cuda_runtime.h>
#include <math.h>
#include <stdint.h>

#define NN 50000
#define HH 128
#define TT 4
#define EE 150000
#define NE (TT*EE)
#define G3H 384

// ---------------- scratch (device globals; no allocation allowed) ----------
__device__ float    g_M[(size_t)TT*NN*HH];
__device__ float    g_inc[(size_t)NN*HH];
__device__ float    g_gx[(size_t)NN*G3H];
__device__ float    g_gh[(size_t)NN*G3H];
__device__ float    g_h[(size_t)NN*HH];
__device__ int      g_cnt[NN];
__device__ int      g_off[NN+1];
__device__ int      g_pos[NN];
__device__ unsigned g_ent[NE];

__device__ __forceinline__ uint32_t f2tf32(float f) {
    uint32_t u;
    asm("cvt.rna.tf32.f32 %0, %1;" : "=r"(u) : "f"(f));
    return u;
}

// ---------------- CSR build ----------------
__global__ void hist_kernel(const int* __restrict__ edges) {
    int i = blockIdx.x * blockDim.x + threadIdx.x;
    if (i < NE) atomicAdd(&g_cnt[edges[2*i+1]], 1);
}

__global__ void scan_kernel() {
    __shared__ int s[1024];
    __shared__ int carry;
    if (threadIdx.x == 0) carry = 0;
    __syncthreads();
    for (int base = 0; base < NN; base += 1024) {
        int i = base + threadIdx.x;
        int v = (i < NN) ? g_cnt[i] : 0;
        s[threadIdx.x] = v;
        __syncthreads();
        #pragma unroll
        for (int off = 1; off < 1024; off <<= 1) {
            int t = (threadIdx.x >= off) ? s[threadIdx.x - off] : 0;
            __syncthreads();
            s[threadIdx.x] += t;
            __syncthreads();
        }
        int excl = carry + s[threadIdx.x] - v;
        if (i < NN) { g_off[i] = excl; g_pos[i] = excl; }
        __syncthreads();
        if (threadIdx.x == 1023) carry += s[1023];
        __syncthreads();
    }
    if (threadIdx.x == 0) g_off[NN] = carry;
}

__global__ void fill_kernel(const int* __restrict__ edges) {
    int i = blockIdx.x * blockDim.x + threadIdx.x;
    if (i < NE) {
        int t   = i / EE;
        int src = edges[2*i];
        int tgt = edges[2*i+1];
        int p = atomicAdd(&g_pos[tgt], 1);
        g_ent[p] = ((unsigned)t << 16) | (unsigned)src;
    }
}

// ---------------- message gather (atomic-free segment sum) ----------------
__global__ void gather_kernel(const float* __restrict__ b) {
    int gw   = (blockIdx.x * blockDim.x + threadIdx.x) >> 5;
    int lane = threadIdx.x & 31;
    if (gw >= NN) return;
    int s = g_off[gw], e = g_off[gw+1];
    float4 acc = make_float4(0.f, 0.f, 0.f, 0.f);
    for (int i = s; i < e; i++) {
        unsigned ent = g_ent[i];
        int t   = (int)(ent >> 16);
        int src = (int)(ent & 0xFFFFu);
        float4 mv = *(const float4*)(g_M + ((size_t)t*NN + src)*HH + lane*4);
        float4 bv = *(const float4*)(b + t*HH + lane*4);
        acc.x += mv.x + bv.x;
        acc.y += mv.y + bv.y;
        acc.z += mv.z + bv.z;
        acc.w += mv.w + bv.w;
    }
    *(float4*)(g_inc + (size_t)gw*HH + lane*4) = acc;
}

// ---------------- tensor-core GEMM via mma.sync tf32 ----------------------
// C = [A0|A1] @ W^T (+bias). CTA tile 128 rows x 128 cols, K chunks of 128.
// 8 warps in 2x4 grid; each warp owns 64x32 via m16n8k8 tf32 MMA.
#define LDPAD 132
__global__ void __launch_bounds__(256, 1)
tgemm_kernel(const float* __restrict__ A0, const float* __restrict__ A1,
             const float* __restrict__ W, int ldW, long long Wystride, int colmult,
             const float* __restrict__ bias,
             float* __restrict__ C, int ldC, long long Cystride)
{
    extern __shared__ uint32_t smem[];
    uint32_t* As = smem;                 // [128][132] tf32 bits
    uint32_t* Ws = smem + 128 * LDPAD;   // [128][132] tf32 bits (Ws[outcol][k])

    const int tid  = threadIdx.x;
    const int lane = tid & 31, warp = tid >> 5;
    const int wm = warp & 1, wn = warp >> 1;     // 2 x 4 warp grid
    const int g  = lane >> 2, t4 = lane & 3;     // quad decomposition
    const int row_base = blockIdx.x * 128;
    const int cb = blockIdx.y * colmult;
    W += (long long)blockIdx.y * Wystride;
    C += (long long)blockIdx.y * Cystride;

    float acc[4][4][4];
    #pragma unroll
    for (int i = 0; i < 4; i++)
        #pragma unroll
        for (int j = 0; j < 4; j++)
            #pragma unroll
            for (int q = 0; q < 4; q++) acc[i][j][q] = 0.f;

    const int nch = (A1 != nullptr) ? 2 : 1;
    for (int ch = 0; ch < nch; ch++) {
        const float* A = ch ? A1 : A0;
        // stage A tile: 128 rows x 128 k (tf32-rounded)
        #pragma unroll
        for (int it = 0; it < 16; it++) {
            int idx = tid + it * 256;
            int r = idx >> 5, q = idx & 31;
            float4 v = make_float4(0.f, 0.f, 0.f, 0.f);
            int gr = row_base + r;
            if (gr < NN) v = *(const float4*)(A + (size_t)gr * HH + q * 4);
            uint32_t* d = As + r * LDPAD + q * 4;
            d[0] = f2tf32(v.x); d[1] = f2tf32(v.y);
            d[2] = f2tf32(v.z); d[3] = f2tf32(v.w);
        }
        // stage W tile: 128 output-cols x 128 k
        #pragma unroll
        for (int it = 0; it < 16; it++) {
            int idx = tid + it * 256;
            int f = idx >> 5, q = idx & 31;
            float4 v = *(const float4*)(W + (size_t)(cb + f) * ldW + ch * 128 + q * 4);
            uint32_t* d = Ws + f * LDPAD + q * 4;
            d[0] = f2tf32(v.x); d[1] = f2tf32(v.y);
            d[2] = f2tf32(v.z); d[3] = f2tf32(v.w);
        }
        __syncthreads();

        #pragma unroll 4
        for (int k0 = 0; k0 < 128; k0 += 8) {
            uint32_t b[4][2], a[4][4];
            #pragma unroll
            for (int j = 0; j < 4; j++) {
                int col = wn * 32 + j * 8 + g;
                b[j][0] = Ws[col * LDPAD + k0 + t4];
                b[j][1] = Ws[col * LDPAD + k0 + 4 + t4];
            }
            #pragma unroll
            for (int i = 0; i < 4; i++) {
                int row = wm * 64 + i * 16 + g;
                a[i][0] = As[row * LDPAD + k0 + t4];
                a[i][1] = As[(row + 8) * LDPAD + k0 + t4];
                a[i][2] = As[row * LDPAD + k0 + 4 + t4];
                a[i][3] = As[(row + 8) * LDPAD + k0 + 4 + t4];
            }
            #pragma unroll
            for (int i = 0; i < 4; i++)
                #pragma unroll
                for (int j = 0; j < 4; j++)
                    asm volatile(
                        "mma.sync.aligned.m16n8k8.row.col.f32.tf32.tf32.f32 "
                        "{%0,%1,%2,%3}, {%4,%5,%6,%7}, {%8,%9}, {%0,%1,%2,%3};"
                        : "+f"(acc[i][j][0]), "+f"(acc[i][j][1]),
                          "+f"(acc[i][j][2]), "+f"(acc[i][j][3])
                        : "r"(a[i][0]), "r"(a[i][1]), "r"(a[i][2]), "r"(a[i][3]),
                          "r"(b[j][0]), "r"(b[j][1]));
        }
        __syncthreads();
    }

    // epilogue: c0/c1 at (row, 2*t4), c2/c3 at (row+8, 2*t4)
    #pragma unroll
    for (int i = 0; i < 4; i++) {
        int r0 = row_base + wm * 64 + i * 16 + g;
        #pragma unroll
        for (int j = 0; j < 4; j++) {
            int col = cb + wn * 32 + j * 8 + 2 * t4;
            float b0 = bias ? bias[col]     : 0.f;
            float b1 = bias ? bias[col + 1] : 0.f;
            if (r0 < NN)
                *(float2*)(C + (size_t)r0 * ldC + col) =
                    make_float2(acc[i][j][0] + b0, acc[i][j][1] + b1);
            if (r0 + 8 < NN)
                *(float2*)(C + (size_t)(r0 + 8) * ldC + col) =
                    make_float2(acc[i][j][2] + b0, acc[i][j][3] + b1);
        }
    }
}

// ---------------- fused GRU gate ----------------
__global__ void gate_kernel(const float* __restrict__ h, float* __restrict__ hout) {
    int idx = blockIdx.x * blockDim.x + threadIdx.x;
    if (idx >= NN * HH) return;
    int n = idx >> 7, f = idx & 127;
    const float* gx = g_gx + (size_t)n * G3H;
    const float* gh = g_gh + (size_t)n * G3H;
    float xr = gx[f], xz = gx[HH + f], xn = gx[2 * HH + f];
    float hr = gh[f], hz = gh[HH + f], hn = gh[2 * HH + f];
    float r = 1.f / (1.f + expf(-(xr + hr)));
    float z = 1.f / (1.f + expf(-(xz + hz)));
    float nv = tanhf(xn + r * hn);
    hout[idx] = (1.f - z) * nv + z * h[idx];
}

// ---------------- launch ----------------
extern "C" void kernel_launch(void* const* d_in, const int* in_sizes, int n_in,
                              void* d_out, int out_size) {
    const float* x      = (const float*)d_in[0];
    const int*   edges  = (const int*)  d_in[1];
    const float* msg_W  = (const float*)d_in[2];
    const float* msg_b  = (const float*)d_in[3];
    const float* g0_Wih = (const float*)d_in[4];
    const float* g0_Whh = (const float*)d_in[5];
    const float* g0_bih = (const float*)d_in[6];
    const float* g0_bhh = (const float*)d_in[7];
    const float* g1_Wih = (const float*)d_in[8];
    const float* g1_Whh = (const float*)d_in[9];
    const float* g1_bih = (const float*)d_in[10];
    const float* g1_bhh = (const float*)d_in[11];

    float *pM, *pInc, *pGx, *pGh, *pH; int *pCnt;
    cudaGetSymbolAddress((void**)&pM,   g_M);
    cudaGetSymbolAddress((void**)&pInc, g_inc);
    cudaGetSymbolAddress((void**)&pGx,  g_gx);
    cudaGetSymbolAddress((void**)&pGh,  g_gh);
    cudaGetSymbolAddress((void**)&pH,   g_h);
    cudaGetSymbolAddress((void**)&pCnt, g_cnt);

    const int SMEM = 2 * 128 * LDPAD * 4;   // 135168 B
    cudaFuncSetAttribute(tgemm_kernel,
                         cudaFuncAttributeMaxDynamicSharedMemorySize, SMEM);

    // CSR build (reused by all 6 timesteps)
    cudaMemsetAsync(pCnt, 0, NN * sizeof(int), 0);
    hist_kernel<<<(NE + 255) / 256, 256>>>(edges);
    scan_kernel<<<1, 1024>>>();
    fill_kernel<<<(NE + 255) / 256, 256>>>(edges);

    // h = x
    cudaMemcpyAsync(pH, x, (size_t)NN * HH * sizeof(float),
                    cudaMemcpyDeviceToDevice, 0);

    const int GX = (NN + 127) / 128;   // 391
    for (int l = 0; l < 2; l++) {
        for (int s = 0; s < 3; s++) {
            // per-type node transform: M[t] = h @ W[l][t]^T
            tgemm_kernel<<<dim3(GX, TT), 256, SMEM>>>(
                pH, nullptr,
                msg_W + (size_t)l * TT * HH * HH, HH, (long long)HH * HH, 0,
                nullptr,
                pM, HH, (long long)NN * HH);
            // inc = segment_sum(M[t][src] + b[t])
            gather_kernel<<<(NN * 32) / 256, 256>>>(msg_b + (size_t)l * TT * HH);
            // GRU GEMMs
            if (l == 0) {
                tgemm_kernel<<<dim3(GX, 3), 256, SMEM>>>(
                    pInc, nullptr, g0_Wih, HH, 0LL, 128, g0_bih, pGx, G3H, 0LL);
                tgemm_kernel<<<dim3(GX, 3), 256, SMEM>>>(
                    pH, nullptr, g0_Whh, HH, 0LL, 128, g0_bhh, pGh, G3H, 0LL);
            } else {
                tgemm_kernel<<<dim3(GX, 3), 256, SMEM>>>(
                    x, pInc, g1_Wih, 2 * HH, 0LL, 128, g1_bih, pGx, G3H, 0LL);
                tgemm_kernel<<<dim3(GX, 3), 256, SMEM>>>(
                    pH, nullptr, g1_Whh, HH, 0LL, 128, g1_bhh, pGh, G3H, 0LL);
            }
            bool last = (l == 1 && s == 2);
            gate_kernel<<<(NN * HH + 255) / 256, 256>>>(pH, last ? (float*)d_out : pH);
        }
    }
}

// round 4
// speedup vs baseline: 4.0628x; 1.3747x over previous
#include <cuda_runtime.h>
#include <cuda_fp16.h>
#include <math.h>
#include <stdint.h>

#define NN 50000
#define HH 128
#define TT 4
#define EE 150000
#define NE (TT*EE)
#define G3H 384
#define TPAD 136   // halves per smem tile row

// ---------------- scratch (device globals; no allocation allowed) ----------
__device__ float    g_M[(size_t)TT*NN*HH];
__device__ float    g_gx[(size_t)NN*G3H];
__device__ float    g_gh[(size_t)NN*G3H];
__device__ float    g_h[(size_t)NN*HH];
__device__ __half   g_h16[(size_t)NN*HH];
__device__ __half   g_x16[(size_t)NN*HH];
__device__ __half   g_inc16[(size_t)NN*HH];
__device__ __half   g_w16[376832];
__device__ int      g_cnt[NN];
__device__ int      g_off[NN+1];
__device__ int      g_pos[NN];
__device__ unsigned g_ent[NE];

// fp16 weight buffer offsets (halves)
#define OFF_MSGW  0        // 2*4*128*128 = 131072
#define OFF_W0IH  131072   // 384*128 = 49152
#define OFF_W0HH  180224   // 49152
#define OFF_W1IH  229376   // 384*256 = 98304
#define OFF_W1HH  327680   // 49152

__device__ __forceinline__ uint32_t smem_u32(const void* p) {
    uint32_t a;
    asm("{ .reg .u64 t; cvta.to.shared.u64 t, %1; cvt.u32.u64 %0, t; }" : "=r"(a) : "l"(p));
    return a;
}

// ---------------- fp32 -> fp16 convert ----------------
__global__ void f2h_kernel(const float* __restrict__ src, __half* __restrict__ dst, int n) {
    int i = blockIdx.x * blockDim.x + threadIdx.x;
    if (i < n) dst[i] = __float2half_rn(src[i]);
}

// ---------------- CSR build ----------------
__global__ void hist_kernel(const int* __restrict__ edges) {
    int i = blockIdx.x * blockDim.x + threadIdx.x;
    if (i < NE) atomicAdd(&g_cnt[edges[2*i+1]], 1);
}

__global__ void scan_kernel() {
    __shared__ int s[1024];
    __shared__ int carry;
    if (threadIdx.x == 0) carry = 0;
    __syncthreads();
    for (int base = 0; base < NN; base += 1024) {
        int i = base + threadIdx.x;
        int v = (i < NN) ? g_cnt[i] : 0;
        s[threadIdx.x] = v;
        __syncthreads();
        #pragma unroll
        for (int off = 1; off < 1024; off <<= 1) {
            int t = (threadIdx.x >= off) ? s[threadIdx.x - off] : 0;
            __syncthreads();
            s[threadIdx.x] += t;
            __syncthreads();
        }
        int excl = carry + s[threadIdx.x] - v;
        if (i < NN) { g_off[i] = excl; g_pos[i] = excl; }
        __syncthreads();
        if (threadIdx.x == 1023) carry += s[1023];
        __syncthreads();
    }
    if (threadIdx.x == 0) g_off[NN] = carry;
}

__global__ void fill_kernel(const int* __restrict__ edges) {
    int i = blockIdx.x * blockDim.x + threadIdx.x;
    if (i < NE) {
        int t   = i / EE;
        int src = edges[2*i];
        int tgt = edges[2*i+1];
        int p = atomicAdd(&g_pos[tgt], 1);
        g_ent[p] = ((unsigned)t << 16) | (unsigned)src;
    }
}

// ---------------- message gather: fp32 accum, fp16 out ----------------
__global__ void gather_kernel(const float* __restrict__ b) {
    int gw   = (blockIdx.x * blockDim.x + threadIdx.x) >> 5;
    int lane = threadIdx.x & 31;
    if (gw >= NN) return;
    int s = g_off[gw], e = g_off[gw+1];
    float4 acc = make_float4(0.f, 0.f, 0.f, 0.f);
    for (int i = s; i < e; i++) {
        unsigned ent = g_ent[i];
        int t   = (int)(ent >> 16);
        int src = (int)(ent & 0xFFFFu);
        float4 mv = *(const float4*)(g_M + ((size_t)t*NN + src)*HH + lane*4);
        float4 bv = *(const float4*)(b + t*HH + lane*4);
        acc.x += mv.x + bv.x;
        acc.y += mv.y + bv.y;
        acc.z += mv.z + bv.z;
        acc.w += mv.w + bv.w;
    }
    __half2 p0 = __floats2half2_rn(acc.x, acc.y);
    __half2 p1 = __floats2half2_rn(acc.z, acc.w);
    uint2 pk = make_uint2(*(uint32_t*)&p0, *(uint32_t*)&p1);
    *(uint2*)(g_inc16 + (size_t)gw*HH + lane*4) = pk;
}

// ---------------- fp16 tensor-core GEMM: C = [A0|A1] @ W^T (+bias) -------
// CTA 128x128 tile, K chunks of 128 (fp16). 8 warps 2x4, each 64x32 via
// mma.sync m16n8k16. cp.async staging, 2 CTAs/SM.
__global__ void __launch_bounds__(256, 2)
tgemm16_kernel(const __half* __restrict__ A0, const __half* __restrict__ A1,
               const __half* __restrict__ W, int ldW, long long Wystride, int colmult,
               const float* __restrict__ bias,
               float* __restrict__ C, int ldC, long long Cystride)
{
    extern __shared__ __half smem[];
    __half* As = smem;                // [128][136]
    __half* Ws = smem + 128 * TPAD;   // [128][136]

    const int tid  = threadIdx.x;
    const int lane = tid & 31, warp = tid >> 5;
    const int wm = warp & 1, wn = warp >> 1;
    const int g  = lane >> 2, t4 = lane & 3;
    const int row_base = blockIdx.x * 128;
    const int cb = blockIdx.y * colmult;
    W += (long long)blockIdx.y * Wystride;
    C += (long long)blockIdx.y * Cystride;

    const uint32_t sAs = smem_u32(As);
    const uint32_t sWs = smem_u32(Ws);

    float acc[4][4][4];
    #pragma unroll
    for (int i = 0; i < 4; i++)
        #pragma unroll
        for (int j = 0; j < 4; j++)
            #pragma unroll
            for (int q = 0; q < 4; q++) acc[i][j][q] = 0.f;

    const int nch = (A1 != nullptr) ? 2 : 1;
    for (int ch = 0; ch < nch; ch++) {
        const __half* A = ch ? A1 : A0;
        // stage A: 128 rows x 128 halves = 2048 x 16B chunks
        #pragma unroll
        for (int it = 0; it < 8; it++) {
            int idx = tid + it * 256;
            int r = idx >> 4, c8 = idx & 15;
            int gr = row_base + r;
            const __half* src = A + (size_t)(gr < NN ? gr : 0) * HH + c8 * 8;
            uint32_t dst = sAs + (r * TPAD + c8 * 8) * 2;
            int sz = (gr < NN) ? 16 : 0;
            asm volatile("cp.async.cg.shared.global [%0], [%1], 16, %2;"
                         :: "r"(dst), "l"(src), "r"(sz));
        }
        // stage W: 128 out-cols x 128 k halves
        #pragma unroll
        for (int it = 0; it < 8; it++) {
            int idx = tid + it * 256;
            int f = idx >> 4, c8 = idx & 15;
            const __half* src = W + (size_t)(cb + f) * ldW + ch * 128 + c8 * 8;
            uint32_t dst = sWs + (f * TPAD + c8 * 8) * 2;
            asm volatile("cp.async.cg.shared.global [%0], [%1], 16, 16;"
                         :: "r"(dst), "l"(src));
        }
        asm volatile("cp.async.commit_group;");
        asm volatile("cp.async.wait_group 0;" ::: "memory");
        __syncthreads();

        #pragma unroll 2
        for (int ks = 0; ks < 8; ks++) {
            int k0 = ks * 16;
            uint32_t b[4][2], a[4][4];
            #pragma unroll
            for (int j = 0; j < 4; j++) {
                const __half* p = Ws + (wn * 32 + j * 8 + g) * TPAD + k0 + 2 * t4;
                b[j][0] = *(const uint32_t*)p;
                b[j][1] = *(const uint32_t*)(p + 8);
            }
            #pragma unroll
            for (int i = 0; i < 4; i++) {
                const __half* p = As + (wm * 64 + i * 16 + g) * TPAD + k0 + 2 * t4;
                a[i][0] = *(const uint32_t*)p;
                a[i][1] = *(const uint32_t*)(p + 8 * TPAD);
                a[i][2] = *(const uint32_t*)(p + 8);
                a[i][3] = *(const uint32_t*)(p + 8 * TPAD + 8);
            }
            #pragma unroll
            for (int i = 0; i < 4; i++)
                #pragma unroll
                for (int j = 0; j < 4; j++)
                    asm volatile(
                        "mma.sync.aligned.m16n8k16.row.col.f32.f16.f16.f32 "
                        "{%0,%1,%2,%3}, {%4,%5,%6,%7}, {%8,%9}, {%0,%1,%2,%3};"
                        : "+f"(acc[i][j][0]), "+f"(acc[i][j][1]),
                          "+f"(acc[i][j][2]), "+f"(acc[i][j][3])
                        : "r"(a[i][0]), "r"(a[i][1]), "r"(a[i][2]), "r"(a[i][3]),
                          "r"(b[j][0]), "r"(b[j][1]));
        }
        __syncthreads();
    }

    #pragma unroll
    for (int i = 0; i < 4; i++) {
        int r0 = row_base + wm * 64 + i * 16 + g;
        #pragma unroll
        for (int j = 0; j < 4; j++) {
            int col = cb + wn * 32 + j * 8 + 2 * t4;
            float b0 = bias ? bias[col]     : 0.f;
            float b1 = bias ? bias[col + 1] : 0.f;
            if (r0 < NN)
                *(float2*)(C + (size_t)r0 * ldC + col) =
                    make_float2(acc[i][j][0] + b0, acc[i][j][1] + b1);
            if (r0 + 8 < NN)
                *(float2*)(C + (size_t)(r0 + 8) * ldC + col) =
                    make_float2(acc[i][j][2] + b0, acc[i][j][3] + b1);
        }
    }
}

// ---------------- fused GRU gate (also emits fp16 h) ----------------
__global__ void gate_kernel(const float* __restrict__ h, float* __restrict__ hout) {
    int idx = blockIdx.x * blockDim.x + threadIdx.x;
    if (idx >= NN * HH) return;
    int n = idx >> 7, f = idx & 127;
    const float* gx = g_gx + (size_t)n * G3H;
    const float* gh = g_gh + (size_t)n * G3H;
    float xr = gx[f], xz = gx[HH + f], xn = gx[2 * HH + f];
    float hr = gh[f], hz = gh[HH + f], hn = gh[2 * HH + f];
    float r = 1.f / (1.f + expf(-(xr + hr)));
    float z = 1.f / (1.f + expf(-(xz + hz)));
    float nv = tanhf(xn + r * hn);
    float out = (1.f - z) * nv + z * h[idx];
    hout[idx] = out;
    g_h16[idx] = __float2half_rn(out);
}

// ---------------- launch ----------------
extern "C" void kernel_launch(void* const* d_in, const int* in_sizes, int n_in,
                              void* d_out, int out_size) {
    const float* x      = (const float*)d_in[0];
    const int*   edges  = (const int*)  d_in[1];
    const float* msg_W  = (const float*)d_in[2];
    const float* msg_b  = (const float*)d_in[3];
    const float* g0_Wih = (const float*)d_in[4];
    const float* g0_Whh = (const float*)d_in[5];
    const float* g0_bih = (const float*)d_in[6];
    const float* g0_bhh = (const float*)d_in[7];
    const float* g1_Wih = (const float*)d_in[8];
    const float* g1_Whh = (const float*)d_in[9];
    const float* g1_bih = (const float*)d_in[10];
    const float* g1_bhh = (const float*)d_in[11];

    float *pM, *pGx, *pGh, *pH; int *pCnt;
    __half *pH16, *pX16, *pInc16, *pW16;
    cudaGetSymbolAddress((void**)&pM,    g_M);
    cudaGetSymbolAddress((void**)&pGx,   g_gx);
    cudaGetSymbolAddress((void**)&pGh,   g_gh);
    cudaGetSymbolAddress((void**)&pH,    g_h);
    cudaGetSymbolAddress((void**)&pCnt,  g_cnt);
    cudaGetSymbolAddress((void**)&pH16,  g_h16);
    cudaGetSymbolAddress((void**)&pX16,  g_x16);
    cudaGetSymbolAddress((void**)&pInc16,g_inc16);
    cudaGetSymbolAddress((void**)&pW16,  g_w16);

    const int SMEM = 2 * 128 * TPAD * 2;   // 69632 B
    cudaFuncSetAttribute(tgemm16_kernel,
                         cudaFuncAttributeMaxDynamicSharedMemorySize, SMEM);

    // one-time conversions
    f2h_kernel<<<(NN*HH + 255)/256, 256>>>(x, pX16, NN*HH);
    f2h_kernel<<<(NN*HH + 255)/256, 256>>>(x, pH16, NN*HH);
    f2h_kernel<<<(131072 + 255)/256, 256>>>(msg_W,  pW16 + OFF_MSGW, 131072);
    f2h_kernel<<<(49152  + 255)/256, 256>>>(g0_Wih, pW16 + OFF_W0IH, 49152);
    f2h_kernel<<<(49152  + 255)/256, 256>>>(g0_Whh, pW16 + OFF_W0HH, 49152);
    f2h_kernel<<<(98304  + 255)/256, 256>>>(g1_Wih, pW16 + OFF_W1IH, 98304);
    f2h_kernel<<<(49152  + 255)/256, 256>>>(g1_Whh, pW16 + OFF_W1HH, 49152);

    // CSR build (reused by all 6 timesteps)
    cudaMemsetAsync(pCnt, 0, NN * sizeof(int), 0);
    hist_kernel<<<(NE + 255) / 256, 256>>>(edges);
    scan_kernel<<<1, 1024>>>();
    fill_kernel<<<(NE + 255) / 256, 256>>>(edges);

    // h = x (fp32 copy for gate residual path)
    cudaMemcpyAsync(pH, x, (size_t)NN * HH * sizeof(float),
                    cudaMemcpyDeviceToDevice, 0);

    const int GX = (NN + 127) / 128;   // 391
    for (int l = 0; l < 2; l++) {
        for (int s = 0; s < 3; s++) {
            // per-type node transform: M[t] = h @ W[l][t]^T
            tgemm16_kernel<<<dim3(GX, TT), 256, SMEM>>>(
                pH16, nullptr,
                pW16 + OFF_MSGW + (size_t)l * TT * HH * HH, HH, (long long)HH * HH, 0,
                nullptr, pM, HH, (long long)NN * HH);
            // Whh GEMM (independent of gather): gh = h @ Whh^T + bhh
            if (l == 0)
                tgemm16_kernel<<<dim3(GX, 3), 256, SMEM>>>(
                    pH16, nullptr, pW16 + OFF_W0HH, HH, 0LL, 128, g0_bhh,
                    pGh, G3H, 0LL);
            else
                tgemm16_kernel<<<dim3(GX, 3), 256, SMEM>>>(
                    pH16, nullptr, pW16 + OFF_W1HH, HH, 0LL, 128, g1_bhh,
                    pGh, G3H, 0LL);
            // inc = segment_sum(M[t][src] + b[t])  -> fp16
            gather_kernel<<<(NN * 32) / 256, 256>>>(msg_b + (size_t)l * TT * HH);
            // Wih GEMM
            if (l == 0)
                tgemm16_kernel<<<dim3(GX, 3), 256, SMEM>>>(
                    pInc16, nullptr, pW16 + OFF_W0IH, HH, 0LL, 128, g0_bih,
                    pGx, G3H, 0LL);
            else
                tgemm16_kernel<<<dim3(GX, 3), 256, SMEM>>>(
                    pX16, pInc16, pW16 + OFF_W1IH, 2 * HH, 0LL, 128, g1_bih,
                    pGx, G3H, 0LL);
            bool last = (l == 1 && s == 2);
            gate_kernel<<<(NN * HH + 255) / 256, 256>>>(pH, last ? (float*)d_out : pH);
        }
    }
}

// round 5
// speedup vs baseline: 4.3702x; 1.0756x over previous
#include <cuda_runtime.h>
#include <cuda_fp16.h>
#include <math.h>
#include <stdint.h>

#define NN 50000
#define HH 128
#define TT 4
#define EE 150000
#define NE (TT*EE)
#define G3H 384
#define TPAD 136   // halves per smem tile row

// ---------------- scratch (device globals; no allocation allowed) ----------
__device__ __half   g_M16[(size_t)TT*NN*HH];
__device__ float    g_gx[(size_t)NN*G3H];
__device__ float    g_gh[(size_t)NN*G3H];
__device__ float    g_h[(size_t)NN*HH];
__device__ __half   g_h16[(size_t)NN*HH];
__device__ __half   g_x16[(size_t)NN*HH];
__device__ __half   g_inc16[(size_t)NN*HH];
__device__ __half   g_w16[376832];
__device__ int      g_cnt[NN];
__device__ int      g_off[NN+1];
__device__ int      g_pos[NN];
__device__ unsigned g_ent[NE];

// fp16 weight buffer offsets (halves)
#define OFF_MSGW  0        // 2*4*128*128 = 131072
#define OFF_W0IH  131072   // 384*128 = 49152
#define OFF_W0HH  180224   // 49152
#define OFF_W1IH  229376   // 384*256 = 98304
#define OFF_W1HH  327680   // 49152

__device__ __forceinline__ uint32_t smem_u32(const void* p) {
    uint32_t a;
    asm("{ .reg .u64 t; cvta.to.shared.u64 t, %1; cvt.u32.u64 %0, t; }" : "=r"(a) : "l"(p));
    return a;
}

// ---------------- fp32 -> fp16 convert ----------------
__global__ void f2h_kernel(const float* __restrict__ src, __half* __restrict__ dst, int n) {
    int i = blockIdx.x * blockDim.x + threadIdx.x;
    if (i < n) dst[i] = __float2half_rn(src[i]);
}

// ---------------- CSR build ----------------
__global__ void hist_kernel(const int* __restrict__ edges) {
    int i = blockIdx.x * blockDim.x + threadIdx.x;
    if (i < NE) atomicAdd(&g_cnt[edges[2*i+1]], 1);
}

__global__ void scan_kernel() {
    __shared__ int s[1024];
    __shared__ int carry;
    if (threadIdx.x == 0) carry = 0;
    __syncthreads();
    for (int base = 0; base < NN; base += 1024) {
        int i = base + threadIdx.x;
        int v = (i < NN) ? g_cnt[i] : 0;
        s[threadIdx.x] = v;
        __syncthreads();
        #pragma unroll
        for (int off = 1; off < 1024; off <<= 1) {
            int t = (threadIdx.x >= off) ? s[threadIdx.x - off] : 0;
            __syncthreads();
            s[threadIdx.x] += t;
            __syncthreads();
        }
        int excl = carry + s[threadIdx.x] - v;
        if (i < NN) { g_off[i] = excl; g_pos[i] = excl; }
        __syncthreads();
        if (threadIdx.x == 1023) carry += s[1023];
        __syncthreads();
    }
    if (threadIdx.x == 0) g_off[NN] = carry;
}

__global__ void fill_kernel(const int* __restrict__ edges) {
    int i = blockIdx.x * blockDim.x + threadIdx.x;
    if (i < NE) {
        int t   = i / EE;
        int src = edges[2*i];
        int tgt = edges[2*i+1];
        int p = atomicAdd(&g_pos[tgt], 1);
        g_ent[p] = ((unsigned)t << 16) | (unsigned)src;
    }
}

// ---------------- message gather: fp16 M, fp32 accum, fp16 out -------------
__global__ void gather_kernel(const float* __restrict__ b) {
    int gw   = (blockIdx.x * blockDim.x + threadIdx.x) >> 5;
    int lane = threadIdx.x & 31;
    if (gw >= NN) return;
    int s = g_off[gw], e = g_off[gw+1];
    float4 acc = make_float4(0.f, 0.f, 0.f, 0.f);
    for (int i = s; i < e; i++) {
        unsigned ent = g_ent[i];
        int t   = (int)(ent >> 16);
        int src = (int)(ent & 0xFFFFu);
        uint2 mv = *(const uint2*)(g_M16 + ((size_t)t*NN + src)*HH + lane*4);
        float2 m0 = __half22float2(*(__half2*)&mv.x);
        float2 m1 = __half22float2(*(__half2*)&mv.y);
        float4 bv = *(const float4*)(b + t*HH + lane*4);
        acc.x += m0.x + bv.x;
        acc.y += m0.y + bv.y;
        acc.z += m1.x + bv.z;
        acc.w += m1.y + bv.w;
    }
    __half2 p0 = __floats2half2_rn(acc.x, acc.y);
    __half2 p1 = __floats2half2_rn(acc.z, acc.w);
    uint2 pk = make_uint2(*(uint32_t*)&p0, *(uint32_t*)&p1);
    *(uint2*)(g_inc16 + (size_t)gw*HH + lane*4) = pk;
}

// ---------------- fused h-GEMM: per-type M (fp16) + gh (fp32) --------------
// A = h16 [NN][128]. blockIdx.y < TT: M[y] = A @ msgW[y]^T (fp16 out).
// blockIdx.y >= TT: gh[:, cb:cb+128] = A @ Whh[cb:,:]^T + bhh (fp32 out).
__global__ void __launch_bounds__(256, 2)
fusedh_kernel(const __half* __restrict__ A,
              const __half* __restrict__ msgW, const __half* __restrict__ whh,
              const float* __restrict__ bhh,
              __half* __restrict__ Mout, float* __restrict__ ghout)
{
    extern __shared__ __half smem[];
    __half* As = smem;
    __half* Ws = smem + 128 * TPAD;

    const int tid  = threadIdx.x;
    const int lane = tid & 31, warp = tid >> 5;
    const int wm = warp & 1, wn = warp >> 1;
    const int g  = lane >> 2, t4 = lane & 3;
    const int row_base = blockIdx.x * 128;
    const bool is_msg = (blockIdx.y < TT);
    const int cb = is_msg ? 0 : (blockIdx.y - TT) * 128;
    const __half* W = is_msg ? (msgW + (size_t)blockIdx.y * HH * HH)
                             : (whh + (size_t)cb * HH);

    const uint32_t sAs = smem_u32(As);
    const uint32_t sWs = smem_u32(Ws);

    float acc[4][4][4];
    #pragma unroll
    for (int i = 0; i < 4; i++)
        #pragma unroll
        for (int j = 0; j < 4; j++)
            #pragma unroll
            for (int q = 0; q < 4; q++) acc[i][j][q] = 0.f;

    #pragma unroll
    for (int it = 0; it < 8; it++) {
        int idx = tid + it * 256;
        int r = idx >> 4, c8 = idx & 15;
        int gr = row_base + r;
        const __half* src = A + (size_t)(gr < NN ? gr : 0) * HH + c8 * 8;
        uint32_t dst = sAs + (r * TPAD + c8 * 8) * 2;
        int sz = (gr < NN) ? 16 : 0;
        asm volatile("cp.async.cg.shared.global [%0], [%1], 16, %2;"
                     :: "r"(dst), "l"(src), "r"(sz));
    }
    #pragma unroll
    for (int it = 0; it < 8; it++) {
        int idx = tid + it * 256;
        int f = idx >> 4, c8 = idx & 15;
        const __half* src = W + (size_t)f * HH + c8 * 8;
        uint32_t dst = sWs + (f * TPAD + c8 * 8) * 2;
        asm volatile("cp.async.cg.shared.global [%0], [%1], 16, 16;"
                     :: "r"(dst), "l"(src));
    }
    asm volatile("cp.async.commit_group;");
    asm volatile("cp.async.wait_group 0;" ::: "memory");
    __syncthreads();

    #pragma unroll 2
    for (int ks = 0; ks < 8; ks++) {
        int k0 = ks * 16;
        uint32_t b[4][2], a[4][4];
        #pragma unroll
        for (int j = 0; j < 4; j++) {
            const __half* p = Ws + (wn * 32 + j * 8 + g) * TPAD + k0 + 2 * t4;
            b[j][0] = *(const uint32_t*)p;
            b[j][1] = *(const uint32_t*)(p + 8);
        }
        #pragma unroll
        for (int i = 0; i < 4; i++) {
            const __half* p = As + (wm * 64 + i * 16 + g) * TPAD + k0 + 2 * t4;
            a[i][0] = *(const uint32_t*)p;
            a[i][1] = *(const uint32_t*)(p + 8 * TPAD);
            a[i][2] = *(const uint32_t*)(p + 8);
            a[i][3] = *(const uint32_t*)(p + 8 * TPAD + 8);
        }
        #pragma unroll
        for (int i = 0; i < 4; i++)
            #pragma unroll
            for (int j = 0; j < 4; j++)
                asm volatile(
                    "mma.sync.aligned.m16n8k16.row.col.f32.f16.f16.f32 "
                    "{%0,%1,%2,%3}, {%4,%5,%6,%7}, {%8,%9}, {%0,%1,%2,%3};"
                    : "+f"(acc[i][j][0]), "+f"(acc[i][j][1]),
                      "+f"(acc[i][j][2]), "+f"(acc[i][j][3])
                    : "r"(a[i][0]), "r"(a[i][1]), "r"(a[i][2]), "r"(a[i][3]),
                      "r"(b[j][0]), "r"(b[j][1]));
    }

    if (is_msg) {
        __half* C = Mout + (size_t)blockIdx.y * NN * HH;
        #pragma unroll
        for (int i = 0; i < 4; i++) {
            int r0 = row_base + wm * 64 + i * 16 + g;
            #pragma unroll
            for (int j = 0; j < 4; j++) {
                int col = wn * 32 + j * 8 + 2 * t4;
                __half2 h0 = __floats2half2_rn(acc[i][j][0], acc[i][j][1]);
                __half2 h1 = __floats2half2_rn(acc[i][j][2], acc[i][j][3]);
                if (r0 < NN)
                    *(uint32_t*)(C + (size_t)r0 * HH + col) = *(uint32_t*)&h0;
                if (r0 + 8 < NN)
                    *(uint32_t*)(C + (size_t)(r0 + 8) * HH + col) = *(uint32_t*)&h1;
            }
        }
    } else {
        #pragma unroll
        for (int i = 0; i < 4; i++) {
            int r0 = row_base + wm * 64 + i * 16 + g;
            #pragma unroll
            for (int j = 0; j < 4; j++) {
                int col = cb + wn * 32 + j * 8 + 2 * t4;
                float b0 = bhh[col], b1 = bhh[col + 1];
                if (r0 < NN)
                    *(float2*)(ghout + (size_t)r0 * G3H + col) =
                        make_float2(acc[i][j][0] + b0, acc[i][j][1] + b1);
                if (r0 + 8 < NN)
                    *(float2*)(ghout + (size_t)(r0 + 8) * G3H + col) =
                        make_float2(acc[i][j][2] + b0, acc[i][j][3] + b1);
            }
        }
    }
}

// ---------------- Wih GEMM: gx = [A0|A1] @ Wih^T + bih (fp32 out) ----------
__global__ void __launch_bounds__(256, 2)
tgemm16_kernel(const __half* __restrict__ A0, const __half* __restrict__ A1,
               const __half* __restrict__ W, int ldW,
               const float* __restrict__ bias, float* __restrict__ C)
{
    extern __shared__ __half smem[];
    __half* As = smem;
    __half* Ws = smem + 128 * TPAD;

    const int tid  = threadIdx.x;
    const int lane = tid & 31, warp = tid >> 5;
    const int wm = warp & 1, wn = warp >> 1;
    const int g  = lane >> 2, t4 = lane & 3;
    const int row_base = blockIdx.x * 128;
    const int cb = blockIdx.y * 128;

    const uint32_t sAs = smem_u32(As);
    const uint32_t sWs = smem_u32(Ws);

    float acc[4][4][4];
    #pragma unroll
    for (int i = 0; i < 4; i++)
        #pragma unroll
        for (int j = 0; j < 4; j++)
            #pragma unroll
            for (int q = 0; q < 4; q++) acc[i][j][q] = 0.f;

    const int nch = (A1 != nullptr) ? 2 : 1;
    for (int ch = 0; ch < nch; ch++) {
        const __half* A = ch ? A1 : A0;
        #pragma unroll
        for (int it = 0; it < 8; it++) {
            int idx = tid + it * 256;
            int r = idx >> 4, c8 = idx & 15;
            int gr = row_base + r;
            const __half* src = A + (size_t)(gr < NN ? gr : 0) * HH + c8 * 8;
            uint32_t dst = sAs + (r * TPAD + c8 * 8) * 2;
            int sz = (gr < NN) ? 16 : 0;
            asm volatile("cp.async.cg.shared.global [%0], [%1], 16, %2;"
                         :: "r"(dst), "l"(src), "r"(sz));
        }
        #pragma unroll
        for (int it = 0; it < 8; it++) {
            int idx = tid + it * 256;
            int f = idx >> 4, c8 = idx & 15;
            const __half* src = W + (size_t)(cb + f) * ldW + ch * 128 + c8 * 8;
            uint32_t dst = sWs + (f * TPAD + c8 * 8) * 2;
            asm volatile("cp.async.cg.shared.global [%0], [%1], 16, 16;"
                         :: "r"(dst), "l"(src));
        }
        asm volatile("cp.async.commit_group;");
        asm volatile("cp.async.wait_group 0;" ::: "memory");
        __syncthreads();

        #pragma unroll 2
        for (int ks = 0; ks < 8; ks++) {
            int k0 = ks * 16;
            uint32_t b[4][2], a[4][4];
            #pragma unroll
            for (int j = 0; j < 4; j++) {
                const __half* p = Ws + (wn * 32 + j * 8 + g) * TPAD + k0 + 2 * t4;
                b[j][0] = *(const uint32_t*)p;
                b[j][1] = *(const uint32_t*)(p + 8);
            }
            #pragma unroll
            for (int i = 0; i < 4; i++) {
                const __half* p = As + (wm * 64 + i * 16 + g) * TPAD + k0 + 2 * t4;
                a[i][0] = *(const uint32_t*)p;
                a[i][1] = *(const uint32_t*)(p + 8 * TPAD);
                a[i][2] = *(const uint32_t*)(p + 8);
                a[i][3] = *(const uint32_t*)(p + 8 * TPAD + 8);
            }
            #pragma unroll
            for (int i = 0; i < 4; i++)
                #pragma unroll
                for (int j = 0; j < 4; j++)
                    asm volatile(
                        "mma.sync.aligned.m16n8k16.row.col.f32.f16.f16.f32 "
                        "{%0,%1,%2,%3}, {%4,%5,%6,%7}, {%8,%9}, {%0,%1,%2,%3};"
                        : "+f"(acc[i][j][0]), "+f"(acc[i][j][1]),
                          "+f"(acc[i][j][2]), "+f"(acc[i][j][3])
                        : "r"(a[i][0]), "r"(a[i][1]), "r"(a[i][2]), "r"(a[i][3]),
                          "r"(b[j][0]), "r"(b[j][1]));
        }
        __syncthreads();
    }

    #pragma unroll
    for (int i = 0; i < 4; i++) {
        int r0 = row_base + wm * 64 + i * 16 + g;
        #pragma unroll
        for (int j = 0; j < 4; j++) {
            int col = cb + wn * 32 + j * 8 + 2 * t4;
            float b0 = bias[col], b1 = bias[col + 1];
            if (r0 < NN)
                *(float2*)(C + (size_t)r0 * G3H + col) =
                    make_float2(acc[i][j][0] + b0, acc[i][j][1] + b1);
            if (r0 + 8 < NN)
                *(float2*)(C + (size_t)(r0 + 8) * G3H + col) =
                    make_float2(acc[i][j][2] + b0, acc[i][j][3] + b1);
        }
    }
}

// ---------------- fused GRU gate (also emits fp16 h) ----------------
__global__ void gate_kernel(const float* __restrict__ h, float* __restrict__ hout) {
    int idx = blockIdx.x * blockDim.x + threadIdx.x;
    if (idx >= NN * HH) return;
    int n = idx >> 7, f = idx & 127;
    const float* gx = g_gx + (size_t)n * G3H;
    const float* gh = g_gh + (size_t)n * G3H;
    float xr = gx[f], xz = gx[HH + f], xn = gx[2 * HH + f];
    float hr = gh[f], hz = gh[HH + f], hn = gh[2 * HH + f];
    float r = 1.f / (1.f + expf(-(xr + hr)));
    float z = 1.f / (1.f + expf(-(xz + hz)));
    float nv = tanhf(xn + r * hn);
    float out = (1.f - z) * nv + z * h[idx];
    hout[idx] = out;
    g_h16[idx] = __float2half_rn(out);
}

// ---------------- launch ----------------
extern "C" void kernel_launch(void* const* d_in, const int* in_sizes, int n_in,
                              void* d_out, int out_size) {
    const float* x      = (const float*)d_in[0];
    const int*   edges  = (const int*)  d_in[1];
    const float* msg_W  = (const float*)d_in[2];
    const float* msg_b  = (const float*)d_in[3];
    const float* g0_Wih = (const float*)d_in[4];
    const float* g0_Whh = (const float*)d_in[5];
    const float* g0_bih = (const float*)d_in[6];
    const float* g0_bhh = (const float*)d_in[7];
    const float* g1_Wih = (const float*)d_in[8];
    const float* g1_Whh = (const float*)d_in[9];
    const float* g1_bih = (const float*)d_in[10];
    const float* g1_bhh = (const float*)d_in[11];

    float *pGx, *pGh, *pH; int *pCnt;
    __half *pM16, *pH16, *pX16, *pInc16, *pW16;
    cudaGetSymbolAddress((void**)&pM16,  g_M16);
    cudaGetSymbolAddress((void**)&pGx,   g_gx);
    cudaGetSymbolAddress((void**)&pGh,   g_gh);
    cudaGetSymbolAddress((void**)&pH,    g_h);
    cudaGetSymbolAddress((void**)&pCnt,  g_cnt);
    cudaGetSymbolAddress((void**)&pH16,  g_h16);
    cudaGetSymbolAddress((void**)&pX16,  g_x16);
    cudaGetSymbolAddress((void**)&pInc16,g_inc16);
    cudaGetSymbolAddress((void**)&pW16,  g_w16);

    const int SMEM = 2 * 128 * TPAD * 2;   // 69632 B
    cudaFuncSetAttribute(fusedh_kernel,
                         cudaFuncAttributeMaxDynamicSharedMemorySize, SMEM);
    cudaFuncSetAttribute(tgemm16_kernel,
                         cudaFuncAttributeMaxDynamicSharedMemorySize, SMEM);

    // one-time conversions
    f2h_kernel<<<(NN*HH + 255)/256, 256>>>(x, pX16, NN*HH);
    f2h_kernel<<<(NN*HH + 255)/256, 256>>>(x, pH16, NN*HH);
    f2h_kernel<<<(131072 + 255)/256, 256>>>(msg_W,  pW16 + OFF_MSGW, 131072);
    f2h_kernel<<<(49152  + 255)/256, 256>>>(g0_Wih, pW16 + OFF_W0IH, 49152);
    f2h_kernel<<<(49152  + 255)/256, 256>>>(g0_Whh, pW16 + OFF_W0HH, 49152);
    f2h_kernel<<<(98304  + 255)/256, 256>>>(g1_Wih, pW16 + OFF_W1IH, 98304);
    f2h_kernel<<<(49152  + 255)/256, 256>>>(g1_Whh, pW16 + OFF_W1HH, 49152);

    // CSR build (reused by all 6 timesteps)
    cudaMemsetAsync(pCnt, 0, NN * sizeof(int), 0);
    hist_kernel<<<(NE + 255) / 256, 256>>>(edges);
    scan_kernel<<<1, 1024>>>();
    fill_kernel<<<(NE + 255) / 256, 256>>>(edges);

    // h = x (fp32 copy for gate residual path)
    cudaMemcpyAsync(pH, x, (size_t)NN * HH * sizeof(float),
                    cudaMemcpyDeviceToDevice, 0);

    const int GX = (NN + 127) / 128;   // 391
    for (int l = 0; l < 2; l++) {
        const __half* whh = pW16 + (l ? OFF_W1HH : OFF_W0HH);
        const float*  bhh = l ? g1_bhh : g0_bhh;
        const float*  bih = l ? g1_bih : g0_bih;
        for (int s = 0; s < 3; s++) {
            // fused: M[t] (fp16) for t<4, gh (fp32) for y>=4
            fusedh_kernel<<<dim3(GX, TT + 3), 256, SMEM>>>(
                pH16, pW16 + OFF_MSGW + (size_t)l * TT * HH * HH,
                whh, bhh, pM16, pGh);
            // inc = segment_sum(M[t][src] + b[t]) -> fp16
            gather_kernel<<<(NN * 32) / 256, 256>>>(msg_b + (size_t)l * TT * HH);
            // gx = [x|inc] @ Wih^T + bih
            if (l == 0)
                tgemm16_kernel<<<dim3(GX, 3), 256, SMEM>>>(
                    pInc16, nullptr, pW16 + OFF_W0IH, HH, bih, pGx);
            else
                tgemm16_kernel<<<dim3(GX, 3), 256, SMEM>>>(
                    pX16, pInc16, pW16 + OFF_W1IH, 2 * HH, bih, pGx);
            bool last = (l == 1 && s == 2);
            gate_kernel<<<(NN * HH + 255) / 256, 256>>>(pH, last ? (float*)d_out : pH);
        }
    }
}

// round 6
// speedup vs baseline: 5.1052x; 1.1682x over previous
#include <cuda_runtime.h>
#include <cuda_fp16.h>
#include <math.h>
#include <stdint.h>

#define NN 50000
#define HH 128
#define TT 4
#define EE 150000
#define NE (TT*EE)
#define G3H 384
#define TPAD 136   // halves per smem tile row

// ---------------- scratch (device globals; no allocation allowed) ----------
__device__ __half   g_M16[(size_t)TT*NN*HH];
__device__ __half   g_gx16[(size_t)NN*G3H];
__device__ __half   g_gh16[(size_t)NN*G3H];
__device__ float    g_h[(size_t)NN*HH];
__device__ __half   g_h16[(size_t)NN*HH];
__device__ __half   g_x16[(size_t)NN*HH];
__device__ __half   g_inc16[(size_t)NN*HH];
__device__ __half   g_w16[376832];
__device__ int      g_cnt[NN];
__device__ int      g_off[NN+1];
__device__ int      g_pos[NN];
__device__ unsigned g_ent[NE];

// fp16 weight buffer offsets (halves)
#define OFF_MSGW  0        // 131072
#define OFF_W0IH  131072   // 49152
#define OFF_W0HH  180224   // 49152
#define OFF_W1IH  229376   // 98304
#define OFF_W1HH  327680   // 49152

__device__ __forceinline__ uint32_t smem_u32(const void* p) {
    uint32_t a;
    asm("{ .reg .u64 t; cvta.to.shared.u64 t, %1; cvt.u32.u64 %0, t; }" : "=r"(a) : "l"(p));
    return a;
}

// ---------------- fused prologue convert ----------------
// x -> g_h (fp32), g_h16, g_x16 ; all weights -> g_w16
__global__ void conv_kernel(const float* __restrict__ x,
                            const float* __restrict__ msgW,
                            const float* __restrict__ w0ih, const float* __restrict__ w0hh,
                            const float* __restrict__ w1ih, const float* __restrict__ w1hh)
{
    int i = blockIdx.x * blockDim.x + threadIdx.x;
    if (i < NN*HH) {
        float v = x[i];
        g_h[i] = v;
        __half hv = __float2half_rn(v);
        g_h16[i] = hv;
        g_x16[i] = hv;
    } else {
        int j = i - NN*HH;
        if (j < 131072)       g_w16[OFF_MSGW + j]            = __float2half_rn(msgW[j]);
        else if (j < 180224)  g_w16[OFF_W0IH + (j - 131072)] = __float2half_rn(w0ih[j - 131072]);
        else if (j < 229376)  g_w16[OFF_W0HH + (j - 180224)] = __float2half_rn(w0hh[j - 180224]);
        else if (j < 327680)  g_w16[OFF_W1IH + (j - 229376)] = __float2half_rn(w1ih[j - 229376]);
        else if (j < 376832)  g_w16[OFF_W1HH + (j - 327680)] = __float2half_rn(w1hh[j - 327680]);
    }
}

// ---------------- CSR build ----------------
__global__ void hist_kernel(const int* __restrict__ edges) {
    int i = blockIdx.x * blockDim.x + threadIdx.x;
    if (i < NE) atomicAdd(&g_cnt[edges[2*i+1]], 1);
}

__global__ void scan_kernel() {
    __shared__ int s[1024];
    __shared__ int carry;
    if (threadIdx.x == 0) carry = 0;
    __syncthreads();
    for (int base = 0; base < NN; base += 1024) {
        int i = base + threadIdx.x;
        int v = (i < NN) ? g_cnt[i] : 0;
        s[threadIdx.x] = v;
        __syncthreads();
        #pragma unroll
        for (int off = 1; off < 1024; off <<= 1) {
            int t = (threadIdx.x >= off) ? s[threadIdx.x - off] : 0;
            __syncthreads();
            s[threadIdx.x] += t;
            __syncthreads();
        }
        int excl = carry + s[threadIdx.x] - v;
        if (i < NN) { g_off[i] = excl; g_pos[i] = excl; }
        __syncthreads();
        if (threadIdx.x == 1023) carry += s[1023];
        __syncthreads();
    }
    if (threadIdx.x == 0) g_off[NN] = carry;
}

__global__ void fill_kernel(const int* __restrict__ edges) {
    int i = blockIdx.x * blockDim.x + threadIdx.x;
    if (i < NE) {
        int t   = i / EE;
        int src = edges[2*i];
        int tgt = edges[2*i+1];
        int p = atomicAdd(&g_pos[tgt], 1);
        g_ent[p] = ((unsigned)t << 16) | (unsigned)src;
    }
}

// ---------------- message gather: fp16 M, fp32 accum, fp16 out -------------
__global__ void gather_kernel(const float* __restrict__ b) {
    __shared__ float sb[TT*HH];
    for (int i = threadIdx.x; i < TT*HH; i += blockDim.x) sb[i] = b[i];
    __syncthreads();

    int gw   = (blockIdx.x * blockDim.x + threadIdx.x) >> 5;
    int lane = threadIdx.x & 31;
    if (gw >= NN) return;
    int s = g_off[gw], e = g_off[gw+1];
    float4 acc = make_float4(0.f, 0.f, 0.f, 0.f);
    for (int i = s; i < e; i++) {
        unsigned ent = g_ent[i];
        int t   = (int)(ent >> 16);
        int src = (int)(ent & 0xFFFFu);
        uint2 mv = *(const uint2*)(g_M16 + ((size_t)t*NN + src)*HH + lane*4);
        float2 m0 = __half22float2(*(__half2*)&mv.x);
        float2 m1 = __half22float2(*(__half2*)&mv.y);
        float4 bv = *(const float4*)(sb + t*HH + lane*4);
        acc.x += m0.x + bv.x;
        acc.y += m0.y + bv.y;
        acc.z += m1.x + bv.z;
        acc.w += m1.y + bv.w;
    }
    __half2 p0 = __floats2half2_rn(acc.x, acc.y);
    __half2 p1 = __floats2half2_rn(acc.z, acc.w);
    uint2 pk = make_uint2(*(uint32_t*)&p0, *(uint32_t*)&p1);
    *(uint2*)(g_inc16 + (size_t)gw*HH + lane*4) = pk;
}

// ---------------- fused h-GEMM: per-type M (fp16) + gh (fp16) --------------
__global__ void __launch_bounds__(256, 2)
fusedh_kernel(const __half* __restrict__ A,
              const __half* __restrict__ msgW, const __half* __restrict__ whh,
              const float* __restrict__ bhh,
              __half* __restrict__ Mout, __half* __restrict__ ghout)
{
    extern __shared__ __half smem[];
    __half* As = smem;
    __half* Ws = smem + 128 * TPAD;

    const int tid  = threadIdx.x;
    const int lane = tid & 31, warp = tid >> 5;
    const int wm = warp & 1, wn = warp >> 1;
    const int g  = lane >> 2, t4 = lane & 3;
    const int row_base = blockIdx.x * 128;
    const bool is_msg = (blockIdx.y < TT);
    const int cb = is_msg ? 0 : (blockIdx.y - TT) * 128;
    const __half* W = is_msg ? (msgW + (size_t)blockIdx.y * HH * HH)
                             : (whh + (size_t)cb * HH);

    const uint32_t sAs = smem_u32(As);
    const uint32_t sWs = smem_u32(Ws);

    float acc[4][4][4];
    #pragma unroll
    for (int i = 0; i < 4; i++)
        #pragma unroll
        for (int j = 0; j < 4; j++)
            #pragma unroll
            for (int q = 0; q < 4; q++) acc[i][j][q] = 0.f;

    #pragma unroll
    for (int it = 0; it < 8; it++) {
        int idx = tid + it * 256;
        int r = idx >> 4, c8 = idx & 15;
        int gr = row_base + r;
        const __half* src = A + (size_t)(gr < NN ? gr : 0) * HH + c8 * 8;
        uint32_t dst = sAs + (r * TPAD + c8 * 8) * 2;
        int sz = (gr < NN) ? 16 : 0;
        asm volatile("cp.async.cg.shared.global [%0], [%1], 16, %2;"
                     :: "r"(dst), "l"(src), "r"(sz));
    }
    #pragma unroll
    for (int it = 0; it < 8; it++) {
        int idx = tid + it * 256;
        int f = idx >> 4, c8 = idx & 15;
        const __half* src = W + (size_t)f * HH + c8 * 8;
        uint32_t dst = sWs + (f * TPAD + c8 * 8) * 2;
        asm volatile("cp.async.cg.shared.global [%0], [%1], 16, 16;"
                     :: "r"(dst), "l"(src));
    }
    asm volatile("cp.async.commit_group;");
    asm volatile("cp.async.wait_group 0;" ::: "memory");
    __syncthreads();

    #pragma unroll 2
    for (int ks = 0; ks < 8; ks++) {
        int k0 = ks * 16;
        uint32_t b[4][2], a[4][4];
        #pragma unroll
        for (int j = 0; j < 4; j++) {
            const __half* p = Ws + (wn * 32 + j * 8 + g) * TPAD + k0 + 2 * t4;
            b[j][0] = *(const uint32_t*)p;
            b[j][1] = *(const uint32_t*)(p + 8);
        }
        #pragma unroll
        for (int i = 0; i < 4; i++) {
            const __half* p = As + (wm * 64 + i * 16 + g) * TPAD + k0 + 2 * t4;
            a[i][0] = *(const uint32_t*)p;
            a[i][1] = *(const uint32_t*)(p + 8 * TPAD);
            a[i][2] = *(const uint32_t*)(p + 8);
            a[i][3] = *(const uint32_t*)(p + 8 * TPAD + 8);
        }
        #pragma unroll
        for (int i = 0; i < 4; i++)
            #pragma unroll
            for (int j = 0; j < 4; j++)
                asm volatile(
                    "mma.sync.aligned.m16n8k16.row.col.f32.f16.f16.f32 "
                    "{%0,%1,%2,%3}, {%4,%5,%6,%7}, {%8,%9}, {%0,%1,%2,%3};"
                    : "+f"(acc[i][j][0]), "+f"(acc[i][j][1]),
                      "+f"(acc[i][j][2]), "+f"(acc[i][j][3])
                    : "r"(a[i][0]), "r"(a[i][1]), "r"(a[i][2]), "r"(a[i][3]),
                      "r"(b[j][0]), "r"(b[j][1]));
    }

    if (is_msg) {
        __half* C = Mout + (size_t)blockIdx.y * NN * HH;
        #pragma unroll
        for (int i = 0; i < 4; i++) {
            int r0 = row_base + wm * 64 + i * 16 + g;
            #pragma unroll
            for (int j = 0; j < 4; j++) {
                int col = wn * 32 + j * 8 + 2 * t4;
                __half2 h0 = __floats2half2_rn(acc[i][j][0], acc[i][j][1]);
                __half2 h1 = __floats2half2_rn(acc[i][j][2], acc[i][j][3]);
                if (r0 < NN)
                    *(uint32_t*)(C + (size_t)r0 * HH + col) = *(uint32_t*)&h0;
                if (r0 + 8 < NN)
                    *(uint32_t*)(C + (size_t)(r0 + 8) * HH + col) = *(uint32_t*)&h1;
            }
        }
    } else {
        #pragma unroll
        for (int i = 0; i < 4; i++) {
            int r0 = row_base + wm * 64 + i * 16 + g;
            #pragma unroll
            for (int j = 0; j < 4; j++) {
                int col = cb + wn * 32 + j * 8 + 2 * t4;
                float b0 = bhh[col], b1 = bhh[col + 1];
                __half2 h0 = __floats2half2_rn(acc[i][j][0] + b0, acc[i][j][1] + b1);
                __half2 h1 = __floats2half2_rn(acc[i][j][2] + b0, acc[i][j][3] + b1);
                if (r0 < NN)
                    *(uint32_t*)(ghout + (size_t)r0 * G3H + col) = *(uint32_t*)&h0;
                if (r0 + 8 < NN)
                    *(uint32_t*)(ghout + (size_t)(r0 + 8) * G3H + col) = *(uint32_t*)&h1;
            }
        }
    }
}

// ---------------- Wih GEMM: gx = [A0|A1] @ Wih^T + bih (fp16 out) ----------
__global__ void __launch_bounds__(256, 2)
tgemm16_kernel(const __half* __restrict__ A0, const __half* __restrict__ A1,
               const __half* __restrict__ W, int ldW,
               const float* __restrict__ bias, __half* __restrict__ C)
{
    extern __shared__ __half smem[];
    __half* As = smem;
    __half* Ws = smem + 128 * TPAD;

    const int tid  = threadIdx.x;
    const int lane = tid & 31, warp = tid >> 5;
    const int wm = warp & 1, wn = warp >> 1;
    const int g  = lane >> 2, t4 = lane & 3;
    const int row_base = blockIdx.x * 128;
    const int cb = blockIdx.y * 128;

    const uint32_t sAs = smem_u32(As);
    const uint32_t sWs = smem_u32(Ws);

    float acc[4][4][4];
    #pragma unroll
    for (int i = 0; i < 4; i++)
        #pragma unroll
        for (int j = 0; j < 4; j++)
            #pragma unroll
            for (int q = 0; q < 4; q++) acc[i][j][q] = 0.f;

    const int nch = (A1 != nullptr) ? 2 : 1;
    for (int ch = 0; ch < nch; ch++) {
        const __half* A = ch ? A1 : A0;
        #pragma unroll
        for (int it = 0; it < 8; it++) {
            int idx = tid + it * 256;
            int r = idx >> 4, c8 = idx & 15;
            int gr = row_base + r;
            const __half* src = A + (size_t)(gr < NN ? gr : 0) * HH + c8 * 8;
            uint32_t dst = sAs + (r * TPAD + c8 * 8) * 2;
            int sz = (gr < NN) ? 16 : 0;
            asm volatile("cp.async.cg.shared.global [%0], [%1], 16, %2;"
                         :: "r"(dst), "l"(src), "r"(sz));
        }
        #pragma unroll
        for (int it = 0; it < 8; it++) {
            int idx = tid + it * 256;
            int f = idx >> 4, c8 = idx & 15;
            const __half* src = W + (size_t)(cb + f) * ldW + ch * 128 + c8 * 8;
            uint32_t dst = sWs + (f * TPAD + c8 * 8) * 2;
            asm volatile("cp.async.cg.shared.global [%0], [%1], 16, 16;"
                         :: "r"(dst), "l"(src));
        }
        asm volatile("cp.async.commit_group;");
        asm volatile("cp.async.wait_group 0;" ::: "memory");
        __syncthreads();

        #pragma unroll 2
        for (int ks = 0; ks < 8; ks++) {
            int k0 = ks * 16;
            uint32_t b[4][2], a[4][4];
            #pragma unroll
            for (int j = 0; j < 4; j++) {
                const __half* p = Ws + (wn * 32 + j * 8 + g) * TPAD + k0 + 2 * t4;
                b[j][0] = *(const uint32_t*)p;
                b[j][1] = *(const uint32_t*)(p + 8);
            }
            #pragma unroll
            for (int i = 0; i < 4; i++) {
                const __half* p = As + (wm * 64 + i * 16 + g) * TPAD + k0 + 2 * t4;
                a[i][0] = *(const uint32_t*)p;
                a[i][1] = *(const uint32_t*)(p + 8 * TPAD);
                a[i][2] = *(const uint32_t*)(p + 8);
                a[i][3] = *(const uint32_t*)(p + 8 * TPAD + 8);
            }
            #pragma unroll
            for (int i = 0; i < 4; i++)
                #pragma unroll
                for (int j = 0; j < 4; j++)
                    asm volatile(
                        "mma.sync.aligned.m16n8k16.row.col.f32.f16.f16.f32 "
                        "{%0,%1,%2,%3}, {%4,%5,%6,%7}, {%8,%9}, {%0,%1,%2,%3};"
                        : "+f"(acc[i][j][0]), "+f"(acc[i][j][1]),
                          "+f"(acc[i][j][2]), "+f"(acc[i][j][3])
                        : "r"(a[i][0]), "r"(a[i][1]), "r"(a[i][2]), "r"(a[i][3]),
                          "r"(b[j][0]), "r"(b[j][1]));
        }
        __syncthreads();
    }

    #pragma unroll
    for (int i = 0; i < 4; i++) {
        int r0 = row_base + wm * 64 + i * 16 + g;
        #pragma unroll
        for (int j = 0; j < 4; j++) {
            int col = cb + wn * 32 + j * 8 + 2 * t4;
            float b0 = bias[col], b1 = bias[col + 1];
            __half2 h0 = __floats2half2_rn(acc[i][j][0] + b0, acc[i][j][1] + b1);
            __half2 h1 = __floats2half2_rn(acc[i][j][2] + b0, acc[i][j][3] + b1);
            if (r0 < NN)
                *(uint32_t*)(C + (size_t)r0 * G3H + col) = *(uint32_t*)&h0;
            if (r0 + 8 < NN)
                *(uint32_t*)(C + (size_t)(r0 + 8) * G3H + col) = *(uint32_t*)&h1;
        }
    }
}

// ---------------- fused GRU gate: fp16 gx/gh, fp32 h ----------------
// each thread handles 2 adjacent features
__global__ void gate_kernel(const float* __restrict__ h, float* __restrict__ hout) {
    int idx2 = blockIdx.x * blockDim.x + threadIdx.x;
    if (idx2 >= NN * 64) return;
    int n = idx2 >> 6, f2 = idx2 & 63;          // f = 2*f2
    const __half* gx = g_gx16 + (size_t)n * G3H + 2 * f2;
    const __half* gh = g_gh16 + (size_t)n * G3H + 2 * f2;
    float2 xr = __half22float2(*(const __half2*)gx);
    float2 xz = __half22float2(*(const __half2*)(gx + HH));
    float2 xn = __half22float2(*(const __half2*)(gx + 2 * HH));
    float2 hr = __half22float2(*(const __half2*)gh);
    float2 hz = __half22float2(*(const __half2*)(gh + HH));
    float2 hn = __half22float2(*(const __half2*)(gh + 2 * HH));
    float2 hv = *(const float2*)(h + (size_t)n * HH + 2 * f2);

    float r0 = 1.f / (1.f + expf(-(xr.x + hr.x)));
    float r1 = 1.f / (1.f + expf(-(xr.y + hr.y)));
    float z0 = 1.f / (1.f + expf(-(xz.x + hz.x)));
    float z1 = 1.f / (1.f + expf(-(xz.y + hz.y)));
    float n0 = tanhf(xn.x + r0 * hn.x);
    float n1 = tanhf(xn.y + r1 * hn.y);
    float o0 = (1.f - z0) * n0 + z0 * hv.x;
    float o1 = (1.f - z1) * n1 + z1 * hv.y;

    *(float2*)(hout + (size_t)n * HH + 2 * f2) = make_float2(o0, o1);
    __half2 oh = __floats2half2_rn(o0, o1);
    *(uint32_t*)(g_h16 + (size_t)n * HH + 2 * f2) = *(uint32_t*)&oh;
}

// ---------------- launch ----------------
extern "C" void kernel_launch(void* const* d_in, const int* in_sizes, int n_in,
                              void* d_out, int out_size) {
    const float* x      = (const float*)d_in[0];
    const int*   edges  = (const int*)  d_in[1];
    const float* msg_W  = (const float*)d_in[2];
    const float* msg_b  = (const float*)d_in[3];
    const float* g0_Wih = (const float*)d_in[4];
    const float* g0_Whh = (const float*)d_in[5];
    const float* g0_bih = (const float*)d_in[6];
    const float* g0_bhh = (const float*)d_in[7];
    const float* g1_Wih = (const float*)d_in[8];
    const float* g1_Whh = (const float*)d_in[9];
    const float* g1_bih = (const float*)d_in[10];
    const float* g1_bhh = (const float*)d_in[11];

    float *pH; int *pCnt;
    __half *pM16, *pH16, *pX16, *pInc16, *pW16, *pGx16, *pGh16;
    cudaGetSymbolAddress((void**)&pM16,  g_M16);
    cudaGetSymbolAddress((void**)&pGx16, g_gx16);
    cudaGetSymbolAddress((void**)&pGh16, g_gh16);
    cudaGetSymbolAddress((void**)&pH,    g_h);
    cudaGetSymbolAddress((void**)&pCnt,  g_cnt);
    cudaGetSymbolAddress((void**)&pH16,  g_h16);
    cudaGetSymbolAddress((void**)&pX16,  g_x16);
    cudaGetSymbolAddress((void**)&pInc16,g_inc16);
    cudaGetSymbolAddress((void**)&pW16,  g_w16);

    const int SMEM = 2 * 128 * TPAD * 2;   // 69632 B
    cudaFuncSetAttribute(fusedh_kernel,
                         cudaFuncAttributeMaxDynamicSharedMemorySize, SMEM);
    cudaFuncSetAttribute(tgemm16_kernel,
                         cudaFuncAttributeMaxDynamicSharedMemorySize, SMEM);

    // fused prologue: h/h16/x16 + all weight conversions
    {
        int total = NN * HH + 376832;
        conv_kernel<<<(total + 255) / 256, 256>>>(x, msg_W, g0_Wih, g0_Whh,
                                                  g1_Wih, g1_Whh);
    }

    // CSR build (reused by all 6 timesteps)
    cudaMemsetAsync(pCnt, 0, NN * sizeof(int), 0);
    hist_kernel<<<(NE + 255) / 256, 256>>>(edges);
    scan_kernel<<<1, 1024>>>();
    fill_kernel<<<(NE + 255) / 256, 256>>>(edges);

    const int GX = (NN + 127) / 128;   // 391
    for (int l = 0; l < 2; l++) {
        const __half* whh = pW16 + (l ? OFF_W1HH : OFF_W0HH);
        const float*  bhh = l ? g1_bhh : g0_bhh;
        const float*  bih = l ? g1_bih : g0_bih;
        for (int s = 0; s < 3; s++) {
            fusedh_kernel<<<dim3(GX, TT + 3), 256, SMEM>>>(
                pH16, pW16 + OFF_MSGW + (size_t)l * TT * HH * HH,
                whh, bhh, pM16, pGh16);
            gather_kernel<<<(NN * 32) / 256, 256>>>(msg_b + (size_t)l * TT * HH);
            if (l == 0)
                tgemm16_kernel<<<dim3(GX, 3), 256, SMEM>>>(
                    pInc16, nullptr, pW16 + OFF_W0IH, HH, bih, pGx16);
            else
                tgemm16_kernel<<<dim3(GX, 3), 256, SMEM>>>(
                    pX16, pInc16, pW16 + OFF_W1IH, 2 * HH, bih, pGx16);
            bool last = (l == 1 && s == 2);
            gate_kernel<<<(NN * 64 + 255) / 256, 256>>>(pH, last ? (float*)d_out : pH);
        }
    }
}

// round 7
// speedup vs baseline: 5.2185x; 1.0222x over previous
#include <cuda_runtime.h>
#include <cuda_fp16.h>
#include <math.h>
#include <stdint.h>

#define NN 50000
#define HH 128
#define TT 4
#define EE 150000
#define NE (TT*EE)
#define G3H 384
#define TPAD 136   // halves per smem tile row

// ---------------- scratch (device globals; no allocation allowed) ----------
__device__ __half   g_M16[(size_t)TT*NN*HH];
__device__ __half   g_gx16[(size_t)NN*G3H];
__device__ __half   g_gh16[(size_t)NN*G3H];
__device__ float    g_h[(size_t)NN*HH];
__device__ __half   g_h16[(size_t)NN*HH];
__device__ __half   g_x16[(size_t)NN*HH];
__device__ __half   g_inc16[(size_t)NN*HH];
__device__ __half   g_w16[376832];
__device__ int      g_cnt[NN];
__device__ int      g_off[NN+1];
__device__ int      g_pos[NN];
__device__ unsigned g_ent[NE];

// fp16 weight buffer offsets (halves)
#define OFF_MSGW  0        // 131072
#define OFF_W0IH  131072   // 49152
#define OFF_W0HH  180224   // 49152
#define OFF_W1IH  229376   // 98304
#define OFF_W1HH  327680   // 49152

__device__ __forceinline__ uint32_t smem_u32(const void* p) {
    uint32_t a;
    asm("{ .reg .u64 t; cvta.to.shared.u64 t, %1; cvt.u32.u64 %0, t; }" : "=r"(a) : "l"(p));
    return a;
}

// ---------------- fused prologue convert ----------------
__global__ void conv_kernel(const float* __restrict__ x,
                            const float* __restrict__ msgW,
                            const float* __restrict__ w0ih, const float* __restrict__ w0hh,
                            const float* __restrict__ w1ih, const float* __restrict__ w1hh)
{
    int i = blockIdx.x * blockDim.x + threadIdx.x;
    if (i < NN*HH) {
        float v = x[i];
        g_h[i] = v;
        __half hv = __float2half_rn(v);
        g_h16[i] = hv;
        g_x16[i] = hv;
    } else {
        int j = i - NN*HH;
        if (j < 131072)       g_w16[OFF_MSGW + j]            = __float2half_rn(msgW[j]);
        else if (j < 180224)  g_w16[OFF_W0IH + (j - 131072)] = __float2half_rn(w0ih[j - 131072]);
        else if (j < 229376)  g_w16[OFF_W0HH + (j - 180224)] = __float2half_rn(w0hh[j - 180224]);
        else if (j < 327680)  g_w16[OFF_W1IH + (j - 229376)] = __float2half_rn(w1ih[j - 229376]);
        else if (j < 376832)  g_w16[OFF_W1HH + (j - 327680)] = __float2half_rn(w1hh[j - 327680]);
    }
}

// ---------------- CSR build ----------------
__global__ void hist_kernel(const int* __restrict__ edges) {
    int i = blockIdx.x * blockDim.x + threadIdx.x;
    if (i < NE) atomicAdd(&g_cnt[edges[2*i+1]], 1);
}

__global__ void scan_kernel() {
    __shared__ int s[1024];
    __shared__ int carry;
    if (threadIdx.x == 0) carry = 0;
    __syncthreads();
    for (int base = 0; base < NN; base += 1024) {
        int i = base + threadIdx.x;
        int v = (i < NN) ? g_cnt[i] : 0;
        s[threadIdx.x] = v;
        __syncthreads();
        #pragma unroll
        for (int off = 1; off < 1024; off <<= 1) {
            int t = (threadIdx.x >= off) ? s[threadIdx.x - off] : 0;
            __syncthreads();
            s[threadIdx.x] += t;
            __syncthreads();
        }
        int excl = carry + s[threadIdx.x] - v;
        if (i < NN) { g_off[i] = excl; g_pos[i] = excl; }
        __syncthreads();
        if (threadIdx.x == 1023) carry += s[1023];
        __syncthreads();
    }
    if (threadIdx.x == 0) g_off[NN] = carry;
}

__global__ void fill_kernel(const int* __restrict__ edges) {
    int i = blockIdx.x * blockDim.x + threadIdx.x;
    if (i < NE) {
        int t   = i / EE;
        int src = edges[2*i];
        int tgt = edges[2*i+1];
        int p = atomicAdd(&g_pos[tgt], 1);
        g_ent[p] = ((unsigned)t << 16) | (unsigned)src;
    }
}

// ---------------- message gather: unroll-4 for MLP ----------------
__global__ void gather_kernel(const float* __restrict__ b) {
    __shared__ float sb[TT*HH];
    for (int i = threadIdx.x; i < TT*HH; i += blockDim.x) sb[i] = b[i];
    __syncthreads();

    int gw   = (blockIdx.x * blockDim.x + threadIdx.x) >> 5;
    int lane = threadIdx.x & 31;
    if (gw >= NN) return;
    int s = g_off[gw], e = g_off[gw+1];
    float4 acc = make_float4(0.f, 0.f, 0.f, 0.f);

    int i = s;
    for (; i + 4 <= e; i += 4) {
        unsigned e0 = g_ent[i], e1 = g_ent[i+1], e2 = g_ent[i+2], e3 = g_ent[i+3];
        const __half* p0 = g_M16 + ((size_t)(e0 >> 16)*NN + (e0 & 0xFFFFu))*HH + lane*4;
        const __half* p1 = g_M16 + ((size_t)(e1 >> 16)*NN + (e1 & 0xFFFFu))*HH + lane*4;
        const __half* p2 = g_M16 + ((size_t)(e2 >> 16)*NN + (e2 & 0xFFFFu))*HH + lane*4;
        const __half* p3 = g_M16 + ((size_t)(e3 >> 16)*NN + (e3 & 0xFFFFu))*HH + lane*4;
        uint2 m0 = *(const uint2*)p0;
        uint2 m1 = *(const uint2*)p1;
        uint2 m2 = *(const uint2*)p2;
        uint2 m3 = *(const uint2*)p3;
        #pragma unroll
        for (int u = 0; u < 4; u++) {
            uint2 mv = (u == 0) ? m0 : (u == 1) ? m1 : (u == 2) ? m2 : m3;
            unsigned ent = (u == 0) ? e0 : (u == 1) ? e1 : (u == 2) ? e2 : e3;
            float2 a0 = __half22float2(*(__half2*)&mv.x);
            float2 a1 = __half22float2(*(__half2*)&mv.y);
            const float* bp = sb + (ent >> 16)*HH + lane*4;
            acc.x += a0.x + bp[0];
            acc.y += a0.y + bp[1];
            acc.z += a1.x + bp[2];
            acc.w += a1.y + bp[3];
        }
    }
    for (; i < e; i++) {
        unsigned ent = g_ent[i];
        uint2 mv = *(const uint2*)(g_M16 + ((size_t)(ent >> 16)*NN + (ent & 0xFFFFu))*HH + lane*4);
        float2 a0 = __half22float2(*(__half2*)&mv.x);
        float2 a1 = __half22float2(*(__half2*)&mv.y);
        const float* bp = sb + (ent >> 16)*HH + lane*4;
        acc.x += a0.x + bp[0];
        acc.y += a0.y + bp[1];
        acc.z += a1.x + bp[2];
        acc.w += a1.y + bp[3];
    }
    __half2 p0 = __floats2half2_rn(acc.x, acc.y);
    __half2 p1 = __floats2half2_rn(acc.z, acc.w);
    uint2 pk = make_uint2(*(uint32_t*)&p0, *(uint32_t*)&p1);
    *(uint2*)(g_inc16 + (size_t)gw*HH + lane*4) = pk;
}

// ---------------- fused h-GEMM: per-type M (fp16) + gh (fp16) --------------
__global__ void __launch_bounds__(256, 2)
fusedh_kernel(const __half* __restrict__ A,
              const __half* __restrict__ msgW, const __half* __restrict__ whh,
              const float* __restrict__ bhh,
              __half* __restrict__ Mout, __half* __restrict__ ghout)
{
    extern __shared__ __half smem[];
    __half* As = smem;
    __half* Ws = smem + 128 * TPAD;

    const int tid  = threadIdx.x;
    const int lane = tid & 31, warp = tid >> 5;
    const int wm = warp & 1, wn = warp >> 1;
    const int g  = lane >> 2, t4 = lane & 3;
    const int row_base = blockIdx.x * 128;
    const bool is_msg = (blockIdx.y < TT);
    const int cb = is_msg ? 0 : (blockIdx.y - TT) * 128;
    const __half* W = is_msg ? (msgW + (size_t)blockIdx.y * HH * HH)
                             : (whh + (size_t)cb * HH);

    const uint32_t sAs = smem_u32(As);
    const uint32_t sWs = smem_u32(Ws);

    float acc[4][4][4];
    #pragma unroll
    for (int i = 0; i < 4; i++)
        #pragma unroll
        for (int j = 0; j < 4; j++)
            #pragma unroll
            for (int q = 0; q < 4; q++) acc[i][j][q] = 0.f;

    #pragma unroll
    for (int it = 0; it < 8; it++) {
        int idx = tid + it * 256;
        int r = idx >> 4, c8 = idx & 15;
        int gr = row_base + r;
        const __half* src = A + (size_t)(gr < NN ? gr : 0) * HH + c8 * 8;
        uint32_t dst = sAs + (r * TPAD + c8 * 8) * 2;
        int sz = (gr < NN) ? 16 : 0;
        asm volatile("cp.async.cg.shared.global [%0], [%1], 16, %2;"
                     :: "r"(dst), "l"(src), "r"(sz));
    }
    #pragma unroll
    for (int it = 0; it < 8; it++) {
        int idx = tid + it * 256;
        int f = idx >> 4, c8 = idx & 15;
        const __half* src = W + (size_t)f * HH + c8 * 8;
        uint32_t dst = sWs + (f * TPAD + c8 * 8) * 2;
        asm volatile("cp.async.cg.shared.global [%0], [%1], 16, 16;"
                     :: "r"(dst), "l"(src));
    }
    asm volatile("cp.async.commit_group;");
    asm volatile("cp.async.wait_group 0;" ::: "memory");
    __syncthreads();

    #pragma unroll 2
    for (int ks = 0; ks < 8; ks++) {
        int k0 = ks * 16;
        uint32_t b[4][2], a[4][4];
        #pragma unroll
        for (int j = 0; j < 4; j++) {
            const __half* p = Ws + (wn * 32 + j * 8 + g) * TPAD + k0 + 2 * t4;
            b[j][0] = *(const uint32_t*)p;
            b[j][1] = *(const uint32_t*)(p + 8);
        }
        #pragma unroll
        for (int i = 0; i < 4; i++) {
            const __half* p = As + (wm * 64 + i * 16 + g) * TPAD + k0 + 2 * t4;
            a[i][0] = *(const uint32_t*)p;
            a[i][1] = *(const uint32_t*)(p + 8 * TPAD);
            a[i][2] = *(const uint32_t*)(p + 8);
            a[i][3] = *(const uint32_t*)(p + 8 * TPAD + 8);
        }
        #pragma unroll
        for (int i = 0; i < 4; i++)
            #pragma unroll
            for (int j = 0; j < 4; j++)
                asm volatile(
                    "mma.sync.aligned.m16n8k16.row.col.f32.f16.f16.f32 "
                    "{%0,%1,%2,%3}, {%4,%5,%6,%7}, {%8,%9}, {%0,%1,%2,%3};"
                    : "+f"(acc[i][j][0]), "+f"(acc[i][j][1]),
                      "+f"(acc[i][j][2]), "+f"(acc[i][j][3])
                    : "r"(a[i][0]), "r"(a[i][1]), "r"(a[i][2]), "r"(a[i][3]),
                      "r"(b[j][0]), "r"(b[j][1]));
    }

    if (is_msg) {
        __half* C = Mout + (size_t)blockIdx.y * NN * HH;
        #pragma unroll
        for (int i = 0; i < 4; i++) {
            int r0 = row_base + wm * 64 + i * 16 + g;
            #pragma unroll
            for (int j = 0; j < 4; j++) {
                int col = wn * 32 + j * 8 + 2 * t4;
                __half2 h0 = __floats2half2_rn(acc[i][j][0], acc[i][j][1]);
                __half2 h1 = __floats2half2_rn(acc[i][j][2], acc[i][j][3]);
                if (r0 < NN)
                    *(uint32_t*)(C + (size_t)r0 * HH + col) = *(uint32_t*)&h0;
                if (r0 + 8 < NN)
                    *(uint32_t*)(C + (size_t)(r0 + 8) * HH + col) = *(uint32_t*)&h1;
            }
        }
    } else {
        #pragma unroll
        for (int i = 0; i < 4; i++) {
            int r0 = row_base + wm * 64 + i * 16 + g;
            #pragma unroll
            for (int j = 0; j < 4; j++) {
                int col = cb + wn * 32 + j * 8 + 2 * t4;
                float b0 = bhh[col], b1 = bhh[col + 1];
                __half2 h0 = __floats2half2_rn(acc[i][j][0] + b0, acc[i][j][1] + b1);
                __half2 h1 = __floats2half2_rn(acc[i][j][2] + b0, acc[i][j][3] + b1);
                if (r0 < NN)
                    *(uint32_t*)(ghout + (size_t)r0 * G3H + col) = *(uint32_t*)&h0;
                if (r0 + 8 < NN)
                    *(uint32_t*)(ghout + (size_t)(r0 + 8) * G3H + col) = *(uint32_t*)&h1;
            }
        }
    }
}

// ---------------- Wih GEMM: gx = [A0|A1] @ Wih^T + bih (fp16 out) ----------
__global__ void __launch_bounds__(256, 2)
tgemm16_kernel(const __half* __restrict__ A0, const __half* __restrict__ A1,
               const __half* __restrict__ W, int ldW,
               const float* __restrict__ bias, __half* __restrict__ C)
{
    extern __shared__ __half smem[];
    __half* As = smem;
    __half* Ws = smem + 128 * TPAD;

    const int tid  = threadIdx.x;
    const int lane = tid & 31, warp = tid >> 5;
    const int wm = warp & 1, wn = warp >> 1;
    const int g  = lane >> 2, t4 = lane & 3;
    const int row_base = blockIdx.x * 128;
    const int cb = blockIdx.y * 128;

    const uint32_t sAs = smem_u32(As);
    const uint32_t sWs = smem_u32(Ws);

    float acc[4][4][4];
    #pragma unroll
    for (int i = 0; i < 4; i++)
        #pragma unroll
        for (int j = 0; j < 4; j++)
            #pragma unroll
            for (int q = 0; q < 4; q++) acc[i][j][q] = 0.f;

    const int nch = (A1 != nullptr) ? 2 : 1;
    for (int ch = 0; ch < nch; ch++) {
        const __half* A = ch ? A1 : A0;
        #pragma unroll
        for (int it = 0; it < 8; it++) {
            int idx = tid + it * 256;
            int r = idx >> 4, c8 = idx & 15;
            int gr = row_base + r;
            const __half* src = A + (size_t)(gr < NN ? gr : 0) * HH + c8 * 8;
            uint32_t dst = sAs + (r * TPAD + c8 * 8) * 2;
            int sz = (gr < NN) ? 16 : 0;
            asm volatile("cp.async.cg.shared.global [%0], [%1], 16, %2;"
                         :: "r"(dst), "l"(src), "r"(sz));
        }
        #pragma unroll
        for (int it = 0; it < 8; it++) {
            int idx = tid + it * 256;
            int f = idx >> 4, c8 = idx & 15;
            const __half* src = W + (size_t)(cb + f) * ldW + ch * 128 + c8 * 8;
            uint32_t dst = sWs + (f * TPAD + c8 * 8) * 2;
            asm volatile("cp.async.cg.shared.global [%0], [%1], 16, 16;"
                         :: "r"(dst), "l"(src));
        }
        asm volatile("cp.async.commit_group;");
        asm volatile("cp.async.wait_group 0;" ::: "memory");
        __syncthreads();

        #pragma unroll 2
        for (int ks = 0; ks < 8; ks++) {
            int k0 = ks * 16;
            uint32_t b[4][2], a[4][4];
            #pragma unroll
            for (int j = 0; j < 4; j++) {
                const __half* p = Ws + (wn * 32 + j * 8 + g) * TPAD + k0 + 2 * t4;
                b[j][0] = *(const uint32_t*)p;
                b[j][1] = *(const uint32_t*)(p + 8);
            }
            #pragma unroll
            for (int i = 0; i < 4; i++) {
                const __half* p = As + (wm * 64 + i * 16 + g) * TPAD + k0 + 2 * t4;
                a[i][0] = *(const uint32_t*)p;
                a[i][1] = *(const uint32_t*)(p + 8 * TPAD);
                a[i][2] = *(const uint32_t*)(p + 8);
                a[i][3] = *(const uint32_t*)(p + 8 * TPAD + 8);
            }
            #pragma unroll
            for (int i = 0; i < 4; i++)
                #pragma unroll
                for (int j = 0; j < 4; j++)
                    asm volatile(
                        "mma.sync.aligned.m16n8k16.row.col.f32.f16.f16.f32 "
                        "{%0,%1,%2,%3}, {%4,%5,%6,%7}, {%8,%9}, {%0,%1,%2,%3};"
                        : "+f"(acc[i][j][0]), "+f"(acc[i][j][1]),
                          "+f"(acc[i][j][2]), "+f"(acc[i][j][3])
                        : "r"(a[i][0]), "r"(a[i][1]), "r"(a[i][2]), "r"(a[i][3]),
                          "r"(b[j][0]), "r"(b[j][1]));
        }
        __syncthreads();
    }

    #pragma unroll
    for (int i = 0; i < 4; i++) {
        int r0 = row_base + wm * 64 + i * 16 + g;
        #pragma unroll
        for (int j = 0; j < 4; j++) {
            int col = cb + wn * 32 + j * 8 + 2 * t4;
            float b0 = bias[col], b1 = bias[col + 1];
            __half2 h0 = __floats2half2_rn(acc[i][j][0] + b0, acc[i][j][1] + b1);
            __half2 h1 = __floats2half2_rn(acc[i][j][2] + b0, acc[i][j][3] + b1);
            if (r0 < NN)
                *(uint32_t*)(C + (size_t)r0 * G3H + col) = *(uint32_t*)&h0;
            if (r0 + 8 < NN)
                *(uint32_t*)(C + (size_t)(r0 + 8) * G3H + col) = *(uint32_t*)&h1;
        }
    }
}

// ---------------- fused GRU gate: 4 features/thread ----------------
__global__ void gate_kernel(const float* __restrict__ h, float* __restrict__ hout) {
    int idx4 = blockIdx.x * blockDim.x + threadIdx.x;
    if (idx4 >= NN * 32) return;
    int n = idx4 >> 5, f4 = (idx4 & 31) * 4;
    const __half* gx = g_gx16 + (size_t)n * G3H + f4;
    const __half* gh = g_gh16 + (size_t)n * G3H + f4;
    uint2 uxr = *(const uint2*)gx;
    uint2 uxz = *(const uint2*)(gx + HH);
    uint2 uxn = *(const uint2*)(gx + 2 * HH);
    uint2 uhr = *(const uint2*)gh;
    uint2 uhz = *(const uint2*)(gh + HH);
    uint2 uhn = *(const uint2*)(gh + 2 * HH);
    float4 hv = *(const float4*)(h + (size_t)n * HH + f4);

    float o[4], hvv[4] = {hv.x, hv.y, hv.z, hv.w};
    #pragma unroll
    for (int u = 0; u < 2; u++) {
        float2 xr = __half22float2(*(__half2*)(&uxr.x + u));
        float2 xz = __half22float2(*(__half2*)(&uxz.x + u));
        float2 xn = __half22float2(*(__half2*)(&uxn.x + u));
        float2 hr = __half22float2(*(__half2*)(&uhr.x + u));
        float2 hz = __half22float2(*(__half2*)(&uhz.x + u));
        float2 hn = __half22float2(*(__half2*)(&uhn.x + u));
        float r0 = 1.f / (1.f + expf(-(xr.x + hr.x)));
        float r1 = 1.f / (1.f + expf(-(xr.y + hr.y)));
        float z0 = 1.f / (1.f + expf(-(xz.x + hz.x)));
        float z1 = 1.f / (1.f + expf(-(xz.y + hz.y)));
        float n0 = tanhf(xn.x + r0 * hn.x);
        float n1 = tanhf(xn.y + r1 * hn.y);
        o[2*u]   = (1.f - z0) * n0 + z0 * hvv[2*u];
        o[2*u+1] = (1.f - z1) * n1 + z1 * hvv[2*u+1];
    }

    *(float4*)(hout + (size_t)n * HH + f4) = make_float4(o[0], o[1], o[2], o[3]);
    __half2 oh0 = __floats2half2_rn(o[0], o[1]);
    __half2 oh1 = __floats2half2_rn(o[2], o[3]);
    uint2 pk = make_uint2(*(uint32_t*)&oh0, *(uint32_t*)&oh1);
    *(uint2*)(g_h16 + (size_t)n * HH + f4) = pk;
}

// ---------------- launch ----------------
extern "C" void kernel_launch(void* const* d_in, const int* in_sizes, int n_in,
                              void* d_out, int out_size) {
    const float* x      = (const float*)d_in[0];
    const int*   edges  = (const int*)  d_in[1];
    const float* msg_W  = (const float*)d_in[2];
    const float* msg_b  = (const float*)d_in[3];
    const float* g0_Wih = (const float*)d_in[4];
    const float* g0_Whh = (const float*)d_in[5];
    const float* g0_bih = (const float*)d_in[6];
    const float* g0_bhh = (const float*)d_in[7];
    const float* g1_Wih = (const float*)d_in[8];
    const float* g1_Whh = (const float*)d_in[9];
    const float* g1_bih = (const float*)d_in[10];
    const float* g1_bhh = (const float*)d_in[11];

    float *pH; int *pCnt;
    __half *pM16, *pH16, *pX16, *pInc16, *pW16, *pGx16, *pGh16;
    cudaGetSymbolAddress((void**)&pM16,  g_M16);
    cudaGetSymbolAddress((void**)&pGx16, g_gx16);
    cudaGetSymbolAddress((void**)&pGh16, g_gh16);
    cudaGetSymbolAddress((void**)&pH,    g_h);
    cudaGetSymbolAddress((void**)&pCnt,  g_cnt);
    cudaGetSymbolAddress((void**)&pH16,  g_h16);
    cudaGetSymbolAddress((void**)&pX16,  g_x16);
    cudaGetSymbolAddress((void**)&pInc16,g_inc16);
    cudaGetSymbolAddress((void**)&pW16,  g_w16);

    const int SMEM = 2 * 128 * TPAD * 2;   // 69632 B
    cudaFuncSetAttribute(fusedh_kernel,
                         cudaFuncAttributeMaxDynamicSharedMemorySize, SMEM);
    cudaFuncSetAttribute(tgemm16_kernel,
                         cudaFuncAttributeMaxDynamicSharedMemorySize, SMEM);

    {
        int total = NN * HH + 376832;
        conv_kernel<<<(total + 255) / 256, 256>>>(x, msg_W, g0_Wih, g0_Whh,
                                                  g1_Wih, g1_Whh);
    }

    cudaMemsetAsync(pCnt, 0, NN * sizeof(int), 0);
    hist_kernel<<<(NE + 255) / 256, 256>>>(edges);
    scan_kernel<<<1, 1024>>>();
    fill_kernel<<<(NE + 255) / 256, 256>>>(edges);

    const int GX = (NN + 127) / 128;   // 391
    for (int l = 0; l < 2; l++) {
        const __half* whh = pW16 + (l ? OFF_W1HH : OFF_W0HH);
        const float*  bhh = l ? g1_bhh : g0_bhh;
        const float*  bih = l ? g1_bih : g0_bih;
        for (int s = 0; s < 3; s++) {
            fusedh_kernel<<<dim3(GX, TT + 3), 256, SMEM>>>(
                pH16, pW16 + OFF_MSGW + (size_t)l * TT * HH * HH,
                whh, bhh, pM16, pGh16);
            gather_kernel<<<(NN * 32) / 256, 256>>>(msg_b + (size_t)l * TT * HH);
            if (l == 0)
                tgemm16_kernel<<<dim3(GX, 3), 256, SMEM>>>(
                    pInc16, nullptr, pW16 + OFF_W0IH, HH, bih, pGx16);
            else
                tgemm16_kernel<<<dim3(GX, 3), 256, SMEM>>>(
                    pX16, pInc16, pW16 + OFF_W1IH, 2 * HH, bih, pGx16);
            bool last = (l == 1 && s == 2);
            gate_kernel<<<(NN * 32 + 255) / 256, 256>>>(pH, last ? (float*)d_out : pH);
        }
    }
}

// round 8
// speedup vs baseline: 5.2418x; 1.0045x over previous
#include <cuda_runtime.h>
#include <cuda_fp16.h>
#include <math.h>
#include <stdint.h>

#define NN 50000
#define HH 128
#define TT 4
#define EE 150000
#define NE (TT*EE)
#define G3H 384
#define TPAD 136   // halves per smem tile row

// ---------------- scratch (device globals; no allocation allowed) ----------
__device__ __half   g_M16[(size_t)TT*NN*HH];
__device__ __half   g_gx16[(size_t)NN*G3H];
__device__ __half   g_gh16[(size_t)NN*G3H];
__device__ float    g_h[(size_t)NN*HH];
__device__ __half   g_h16[(size_t)NN*HH];
__device__ __half   g_x16[(size_t)NN*HH];
__device__ __half   g_inc16[(size_t)NN*HH];
__device__ __half   g_w16[376832];
__device__ int      g_cnt[NN];
__device__ int      g_off[NN+1];
__device__ int      g_pos[NN];
__device__ unsigned g_ent[NE];

// fp16 weight buffer offsets (halves)
#define OFF_MSGW  0        // 131072
#define OFF_W0IH  131072   // 49152
#define OFF_W0HH  180224   // 49152
#define OFF_W1IH  229376   // 98304
#define OFF_W1HH  327680   // 49152

__device__ __forceinline__ uint32_t smem_u32(const void* p) {
    uint32_t a;
    asm("{ .reg .u64 t; cvta.to.shared.u64 t, %1; cvt.u32.u64 %0, t; }" : "=r"(a) : "l"(p));
    return a;
}

// ---------------- fused prologue convert ----------------
__global__ void conv_kernel(const float* __restrict__ x,
                            const float* __restrict__ msgW,
                            const float* __restrict__ w0ih, const float* __restrict__ w0hh,
                            const float* __restrict__ w1ih, const float* __restrict__ w1hh)
{
    int i = blockIdx.x * blockDim.x + threadIdx.x;
    if (i < NN*HH) {
        float v = x[i];
        g_h[i] = v;
        __half hv = __float2half_rn(v);
        g_h16[i] = hv;
        g_x16[i] = hv;
    } else {
        int j = i - NN*HH;
        if (j < 131072)       g_w16[OFF_MSGW + j]            = __float2half_rn(msgW[j]);
        else if (j < 180224)  g_w16[OFF_W0IH + (j - 131072)] = __float2half_rn(w0ih[j - 131072]);
        else if (j < 229376)  g_w16[OFF_W0HH + (j - 180224)] = __float2half_rn(w0hh[j - 180224]);
        else if (j < 327680)  g_w16[OFF_W1IH + (j - 229376)] = __float2half_rn(w1ih[j - 229376]);
        else if (j < 376832)  g_w16[OFF_W1HH + (j - 327680)] = __float2half_rn(w1hh[j - 327680]);
    }
}

// ---------------- CSR build ----------------
__global__ void hist_kernel(const int* __restrict__ edges) {
    int i = blockIdx.x * blockDim.x + threadIdx.x;
    if (i < NE) atomicAdd(&g_cnt[edges[2*i+1]], 1);
}

__global__ void scan_kernel() {
    __shared__ int s[1024];
    __shared__ int carry;
    if (threadIdx.x == 0) carry = 0;
    __syncthreads();
    for (int base = 0; base < NN; base += 1024) {
        int i = base + threadIdx.x;
        int v = (i < NN) ? g_cnt[i] : 0;
        s[threadIdx.x] = v;
        __syncthreads();
        #pragma unroll
        for (int off = 1; off < 1024; off <<= 1) {
            int t = (threadIdx.x >= off) ? s[threadIdx.x - off] : 0;
            __syncthreads();
            s[threadIdx.x] += t;
            __syncthreads();
        }
        int excl = carry + s[threadIdx.x] - v;
        if (i < NN) { g_off[i] = excl; g_pos[i] = excl; }
        __syncthreads();
        if (threadIdx.x == 1023) carry += s[1023];
        __syncthreads();
    }
    if (threadIdx.x == 0) g_off[NN] = carry;
}

__global__ void fill_kernel(const int* __restrict__ edges) {
    int i = blockIdx.x * blockDim.x + threadIdx.x;
    if (i < NE) {
        int t   = i / EE;
        int src = edges[2*i];
        int tgt = edges[2*i+1];
        int p = atomicAdd(&g_pos[tgt], 1);
        g_ent[p] = ((unsigned)t << 16) | (unsigned)src;
    }
}

// ---------------- message gather: unroll-4 for MLP ----------------
__global__ void gather_kernel(const float* __restrict__ b) {
    __shared__ float sb[TT*HH];
    for (int i = threadIdx.x; i < TT*HH; i += blockDim.x) sb[i] = b[i];
    __syncthreads();

    int gw   = (blockIdx.x * blockDim.x + threadIdx.x) >> 5;
    int lane = threadIdx.x & 31;
    if (gw >= NN) return;
    int s = g_off[gw], e = g_off[gw+1];
    float4 acc = make_float4(0.f, 0.f, 0.f, 0.f);

    int i = s;
    for (; i + 4 <= e; i += 4) {
        unsigned e0 = g_ent[i], e1 = g_ent[i+1], e2 = g_ent[i+2], e3 = g_ent[i+3];
        const __half* p0 = g_M16 + ((size_t)(e0 >> 16)*NN + (e0 & 0xFFFFu))*HH + lane*4;
        const __half* p1 = g_M16 + ((size_t)(e1 >> 16)*NN + (e1 & 0xFFFFu))*HH + lane*4;
        const __half* p2 = g_M16 + ((size_t)(e2 >> 16)*NN + (e2 & 0xFFFFu))*HH + lane*4;
        const __half* p3 = g_M16 + ((size_t)(e3 >> 16)*NN + (e3 & 0xFFFFu))*HH + lane*4;
        uint2 m0 = *(const uint2*)p0;
        uint2 m1 = *(const uint2*)p1;
        uint2 m2 = *(const uint2*)p2;
        uint2 m3 = *(const uint2*)p3;
        #pragma unroll
        for (int u = 0; u < 4; u++) {
            uint2 mv = (u == 0) ? m0 : (u == 1) ? m1 : (u == 2) ? m2 : m3;
            unsigned ent = (u == 0) ? e0 : (u == 1) ? e1 : (u == 2) ? e2 : e3;
            float2 a0 = __half22float2(*(__half2*)&mv.x);
            float2 a1 = __half22float2(*(__half2*)&mv.y);
            const float* bp = sb + (ent >> 16)*HH + lane*4;
            acc.x += a0.x + bp[0];
            acc.y += a0.y + bp[1];
            acc.z += a1.x + bp[2];
            acc.w += a1.y + bp[3];
        }
    }
    for (; i < e; i++) {
        unsigned ent = g_ent[i];
        uint2 mv = *(const uint2*)(g_M16 + ((size_t)(ent >> 16)*NN + (ent & 0xFFFFu))*HH + lane*4);
        float2 a0 = __half22float2(*(__half2*)&mv.x);
        float2 a1 = __half22float2(*(__half2*)&mv.y);
        const float* bp = sb + (ent >> 16)*HH + lane*4;
        acc.x += a0.x + bp[0];
        acc.y += a0.y + bp[1];
        acc.z += a1.x + bp[2];
        acc.w += a1.y + bp[3];
    }
    __half2 p0 = __floats2half2_rn(acc.x, acc.y);
    __half2 p1 = __floats2half2_rn(acc.z, acc.w);
    uint2 pk = make_uint2(*(uint32_t*)&p0, *(uint32_t*)&p1);
    *(uint2*)(g_inc16 + (size_t)gw*HH + lane*4) = pk;
}

// ---------------- fused h-GEMM: per-type M (fp16) + gh (fp16) --------------
// y = blockIdx.y + ybase. y < TT: M[y] = A @ msgW[y]^T. y >= TT: gh block.
__global__ void __launch_bounds__(256, 2)
fusedh_kernel(const __half* __restrict__ A,
              const __half* __restrict__ msgW, const __half* __restrict__ whh,
              const float* __restrict__ bhh,
              __half* __restrict__ Mout, __half* __restrict__ ghout, int ybase)
{
    extern __shared__ __half smem[];
    __half* As = smem;
    __half* Ws = smem + 128 * TPAD;

    const int tid  = threadIdx.x;
    const int lane = tid & 31, warp = tid >> 5;
    const int wm = warp & 1, wn = warp >> 1;
    const int g  = lane >> 2, t4 = lane & 3;
    const int row_base = blockIdx.x * 128;
    const int yy = blockIdx.y + ybase;
    const bool is_msg = (yy < TT);
    const int cb = is_msg ? 0 : (yy - TT) * 128;
    const __half* W = is_msg ? (msgW + (size_t)yy * HH * HH)
                             : (whh + (size_t)cb * HH);

    const uint32_t sAs = smem_u32(As);
    const uint32_t sWs = smem_u32(Ws);

    float acc[4][4][4];
    #pragma unroll
    for (int i = 0; i < 4; i++)
        #pragma unroll
        for (int j = 0; j < 4; j++)
            #pragma unroll
            for (int q = 0; q < 4; q++) acc[i][j][q] = 0.f;

    #pragma unroll
    for (int it = 0; it < 8; it++) {
        int idx = tid + it * 256;
        int r = idx >> 4, c8 = idx & 15;
        int gr = row_base + r;
        const __half* src = A + (size_t)(gr < NN ? gr : 0) * HH + c8 * 8;
        uint32_t dst = sAs + (r * TPAD + c8 * 8) * 2;
        int sz = (gr < NN) ? 16 : 0;
        asm volatile("cp.async.cg.shared.global [%0], [%1], 16, %2;"
                     :: "r"(dst), "l"(src), "r"(sz));
    }
    #pragma unroll
    for (int it = 0; it < 8; it++) {
        int idx = tid + it * 256;
        int f = idx >> 4, c8 = idx & 15;
        const __half* src = W + (size_t)f * HH + c8 * 8;
        uint32_t dst = sWs + (f * TPAD + c8 * 8) * 2;
        asm volatile("cp.async.cg.shared.global [%0], [%1], 16, 16;"
                     :: "r"(dst), "l"(src));
    }
    asm volatile("cp.async.commit_group;");
    asm volatile("cp.async.wait_group 0;" ::: "memory");
    __syncthreads();

    #pragma unroll 2
    for (int ks = 0; ks < 8; ks++) {
        int k0 = ks * 16;
        uint32_t b[4][2], a[4][4];
        #pragma unroll
        for (int j = 0; j < 4; j++) {
            const __half* p = Ws + (wn * 32 + j * 8 + g) * TPAD + k0 + 2 * t4;
            b[j][0] = *(const uint32_t*)p;
            b[j][1] = *(const uint32_t*)(p + 8);
        }
        #pragma unroll
        for (int i = 0; i < 4; i++) {
            const __half* p = As + (wm * 64 + i * 16 + g) * TPAD + k0 + 2 * t4;
            a[i][0] = *(const uint32_t*)p;
            a[i][1] = *(const uint32_t*)(p + 8 * TPAD);
            a[i][2] = *(const uint32_t*)(p + 8);
            a[i][3] = *(const uint32_t*)(p + 8 * TPAD + 8);
        }
        #pragma unroll
        for (int i = 0; i < 4; i++)
            #pragma unroll
            for (int j = 0; j < 4; j++)
                asm volatile(
                    "mma.sync.aligned.m16n8k16.row.col.f32.f16.f16.f32 "
                    "{%0,%1,%2,%3}, {%4,%5,%6,%7}, {%8,%9}, {%0,%1,%2,%3};"
                    : "+f"(acc[i][j][0]), "+f"(acc[i][j][1]),
                      "+f"(acc[i][j][2]), "+f"(acc[i][j][3])
                    : "r"(a[i][0]), "r"(a[i][1]), "r"(a[i][2]), "r"(a[i][3]),
                      "r"(b[j][0]), "r"(b[j][1]));
    }

    if (is_msg) {
        __half* C = Mout + (size_t)yy * NN * HH;
        #pragma unroll
        for (int i = 0; i < 4; i++) {
            int r0 = row_base + wm * 64 + i * 16 + g;
            #pragma unroll
            for (int j = 0; j < 4; j++) {
                int col = wn * 32 + j * 8 + 2 * t4;
                __half2 h0 = __floats2half2_rn(acc[i][j][0], acc[i][j][1]);
                __half2 h1 = __floats2half2_rn(acc[i][j][2], acc[i][j][3]);
                if (r0 < NN)
                    *(uint32_t*)(C + (size_t)r0 * HH + col) = *(uint32_t*)&h0;
                if (r0 + 8 < NN)
                    *(uint32_t*)(C + (size_t)(r0 + 8) * HH + col) = *(uint32_t*)&h1;
            }
        }
    } else {
        #pragma unroll
        for (int i = 0; i < 4; i++) {
            int r0 = row_base + wm * 64 + i * 16 + g;
            #pragma unroll
            for (int j = 0; j < 4; j++) {
                int col = cb + wn * 32 + j * 8 + 2 * t4;
                float b0 = bhh[col], b1 = bhh[col + 1];
                __half2 h0 = __floats2half2_rn(acc[i][j][0] + b0, acc[i][j][1] + b1);
                __half2 h1 = __floats2half2_rn(acc[i][j][2] + b0, acc[i][j][3] + b1);
                if (r0 < NN)
                    *(uint32_t*)(ghout + (size_t)r0 * G3H + col) = *(uint32_t*)&h0;
                if (r0 + 8 < NN)
                    *(uint32_t*)(ghout + (size_t)(r0 + 8) * G3H + col) = *(uint32_t*)&h1;
            }
        }
    }
}

// ---------------- Wih GEMM: gx = [A0|A1] @ Wih^T + bih (fp16 out) ----------
__global__ void __launch_bounds__(256, 2)
tgemm16_kernel(const __half* __restrict__ A0, const __half* __restrict__ A1,
               const __half* __restrict__ W, int ldW,
               const float* __restrict__ bias, __half* __restrict__ C)
{
    extern __shared__ __half smem[];
    __half* As = smem;
    __half* Ws = smem + 128 * TPAD;

    const int tid  = threadIdx.x;
    const int lane = tid & 31, warp = tid >> 5;
    const int wm = warp & 1, wn = warp >> 1;
    const int g  = lane >> 2, t4 = lane & 3;
    const int row_base = blockIdx.x * 128;
    const int cb = blockIdx.y * 128;

    const uint32_t sAs = smem_u32(As);
    const uint32_t sWs = smem_u32(Ws);

    float acc[4][4][4];
    #pragma unroll
    for (int i = 0; i < 4; i++)
        #pragma unroll
        for (int j = 0; j < 4; j++)
            #pragma unroll
            for (int q = 0; q < 4; q++) acc[i][j][q] = 0.f;

    const int nch = (A1 != nullptr) ? 2 : 1;
    for (int ch = 0; ch < nch; ch++) {
        const __half* A = ch ? A1 : A0;
        #pragma unroll
        for (int it = 0; it < 8; it++) {
            int idx = tid + it * 256;
            int r = idx >> 4, c8 = idx & 15;
            int gr = row_base + r;
            const __half* src = A + (size_t)(gr < NN ? gr : 0) * HH + c8 * 8;
            uint32_t dst = sAs + (r * TPAD + c8 * 8) * 2;
            int sz = (gr < NN) ? 16 : 0;
            asm volatile("cp.async.cg.shared.global [%0], [%1], 16, %2;"
                         :: "r"(dst), "l"(src), "r"(sz));
        }
        #pragma unroll
        for (int it = 0; it < 8; it++) {
            int idx = tid + it * 256;
            int f = idx >> 4, c8 = idx & 15;
            const __half* src = W + (size_t)(cb + f) * ldW + ch * 128 + c8 * 8;
            uint32_t dst = sWs + (f * TPAD + c8 * 8) * 2;
            asm volatile("cp.async.cg.shared.global [%0], [%1], 16, 16;"
                         :: "r"(dst), "l"(src));
        }
        asm volatile("cp.async.commit_group;");
        asm volatile("cp.async.wait_group 0;" ::: "memory");
        __syncthreads();

        #pragma unroll 2
        for (int ks = 0; ks < 8; ks++) {
            int k0 = ks * 16;
            uint32_t b[4][2], a[4][4];
            #pragma unroll
            for (int j = 0; j < 4; j++) {
                const __half* p = Ws + (wn * 32 + j * 8 + g) * TPAD + k0 + 2 * t4;
                b[j][0] = *(const uint32_t*)p;
                b[j][1] = *(const uint32_t*)(p + 8);
            }
            #pragma unroll
            for (int i = 0; i < 4; i++) {
                const __half* p = As + (wm * 64 + i * 16 + g) * TPAD + k0 + 2 * t4;
                a[i][0] = *(const uint32_t*)p;
                a[i][1] = *(const uint32_t*)(p + 8 * TPAD);
                a[i][2] = *(const uint32_t*)(p + 8);
                a[i][3] = *(const uint32_t*)(p + 8 * TPAD + 8);
            }
            #pragma unroll
            for (int i = 0; i < 4; i++)
                #pragma unroll
                for (int j = 0; j < 4; j++)
                    asm volatile(
                        "mma.sync.aligned.m16n8k16.row.col.f32.f16.f16.f32 "
                        "{%0,%1,%2,%3}, {%4,%5,%6,%7}, {%8,%9}, {%0,%1,%2,%3};"
                        : "+f"(acc[i][j][0]), "+f"(acc[i][j][1]),
                          "+f"(acc[i][j][2]), "+f"(acc[i][j][3])
                        : "r"(a[i][0]), "r"(a[i][1]), "r"(a[i][2]), "r"(a[i][3]),
                          "r"(b[j][0]), "r"(b[j][1]));
        }
        __syncthreads();
    }

    #pragma unroll
    for (int i = 0; i < 4; i++) {
        int r0 = row_base + wm * 64 + i * 16 + g;
        #pragma unroll
        for (int j = 0; j < 4; j++) {
            int col = cb + wn * 32 + j * 8 + 2 * t4;
            float b0 = bias[col], b1 = bias[col + 1];
            __half2 h0 = __floats2half2_rn(acc[i][j][0] + b0, acc[i][j][1] + b1);
            __half2 h1 = __floats2half2_rn(acc[i][j][2] + b0, acc[i][j][3] + b1);
            if (r0 < NN)
                *(uint32_t*)(C + (size_t)r0 * G3H + col) = *(uint32_t*)&h0;
            if (r0 + 8 < NN)
                *(uint32_t*)(C + (size_t)(r0 + 8) * G3H + col) = *(uint32_t*)&h1;
        }
    }
}

// ---------------- fused GRU gate: 4 features/thread ----------------
__global__ void gate_kernel(const float* __restrict__ h, float* __restrict__ hout) {
    int idx4 = blockIdx.x * blockDim.x + threadIdx.x;
    if (idx4 >= NN * 32) return;
    int n = idx4 >> 5, f4 = (idx4 & 31) * 4;
    const __half* gx = g_gx16 + (size_t)n * G3H + f4;
    const __half* gh = g_gh16 + (size_t)n * G3H + f4;
    uint2 uxr = *(const uint2*)gx;
    uint2 uxz = *(const uint2*)(gx + HH);
    uint2 uxn = *(const uint2*)(gx + 2 * HH);
    uint2 uhr = *(const uint2*)gh;
    uint2 uhz = *(const uint2*)(gh + HH);
    uint2 uhn = *(const uint2*)(gh + 2 * HH);
    float4 hv = *(const float4*)(h + (size_t)n * HH + f4);

    float o[4], hvv[4] = {hv.x, hv.y, hv.z, hv.w};
    #pragma unroll
    for (int u = 0; u < 2; u++) {
        float2 xr = __half22float2(*(__half2*)(&uxr.x + u));
        float2 xz = __half22float2(*(__half2*)(&uxz.x + u));
        float2 xn = __half22float2(*(__half2*)(&uxn.x + u));
        float2 hr = __half22float2(*(__half2*)(&uhr.x + u));
        float2 hz = __half22float2(*(__half2*)(&uhz.x + u));
        float2 hn = __half22float2(*(__half2*)(&uhn.x + u));
        float r0 = 1.f / (1.f + expf(-(xr.x + hr.x)));
        float r1 = 1.f / (1.f + expf(-(xr.y + hr.y)));
        float z0 = 1.f / (1.f + expf(-(xz.x + hz.x)));
        float z1 = 1.f / (1.f + expf(-(xz.y + hz.y)));
        float n0 = tanhf(xn.x + r0 * hn.x);
        float n1 = tanhf(xn.y + r1 * hn.y);
        o[2*u]   = (1.f - z0) * n0 + z0 * hvv[2*u];
        o[2*u+1] = (1.f - z1) * n1 + z1 * hvv[2*u+1];
    }

    *(float4*)(hout + (size_t)n * HH + f4) = make_float4(o[0], o[1], o[2], o[3]);
    __half2 oh0 = __floats2half2_rn(o[0], o[1]);
    __half2 oh1 = __floats2half2_rn(o[2], o[3]);
    uint2 pk = make_uint2(*(uint32_t*)&oh0, *(uint32_t*)&oh1);
    *(uint2*)(g_h16 + (size_t)n * HH + f4) = pk;
}

// ---------------- launch ----------------
extern "C" void kernel_launch(void* const* d_in, const int* in_sizes, int n_in,
                              void* d_out, int out_size) {
    const float* x      = (const float*)d_in[0];
    const int*   edges  = (const int*)  d_in[1];
    const float* msg_W  = (const float*)d_in[2];
    const float* msg_b  = (const float*)d_in[3];
    const float* g0_Wih = (const float*)d_in[4];
    const float* g0_Whh = (const float*)d_in[5];
    const float* g0_bih = (const float*)d_in[6];
    const float* g0_bhh = (const float*)d_in[7];
    const float* g1_Wih = (const float*)d_in[8];
    const float* g1_Whh = (const float*)d_in[9];
    const float* g1_bih = (const float*)d_in[10];
    const float* g1_bhh = (const float*)d_in[11];

    float *pH; int *pCnt;
    __half *pM16, *pH16, *pX16, *pInc16, *pW16, *pGx16, *pGh16;
    cudaGetSymbolAddress((void**)&pM16,  g_M16);
    cudaGetSymbolAddress((void**)&pGx16, g_gx16);
    cudaGetSymbolAddress((void**)&pGh16, g_gh16);
    cudaGetSymbolAddress((void**)&pH,    g_h);
    cudaGetSymbolAddress((void**)&pCnt,  g_cnt);
    cudaGetSymbolAddress((void**)&pH16,  g_h16);
    cudaGetSymbolAddress((void**)&pX16,  g_x16);
    cudaGetSymbolAddress((void**)&pInc16,g_inc16);
    cudaGetSymbolAddress((void**)&pW16,  g_w16);

    const int SMEM = 2 * 128 * TPAD * 2;   // 69632 B
    cudaFuncSetAttribute(fusedh_kernel,
                         cudaFuncAttributeMaxDynamicSharedMemorySize, SMEM);
    cudaFuncSetAttribute(tgemm16_kernel,
                         cudaFuncAttributeMaxDynamicSharedMemorySize, SMEM);

    // side stream + events (created once; identical work enqueued every call)
    static cudaStream_t s1 = nullptr;
    static cudaEvent_t evFork = nullptr, evGh = nullptr, evCsr = nullptr;
    if (s1 == nullptr) {
        cudaStreamCreateWithFlags(&s1, cudaStreamNonBlocking);
        cudaEventCreateWithFlags(&evFork, cudaEventDisableTiming);
        cudaEventCreateWithFlags(&evGh,   cudaEventDisableTiming);
        cudaEventCreateWithFlags(&evCsr,  cudaEventDisableTiming);
    }

    // fork: CSR build on s1, prologue conversion on main stream
    cudaEventRecord(evFork, 0);
    cudaStreamWaitEvent(s1, evFork, 0);
    cudaMemsetAsync(pCnt, 0, NN * sizeof(int), s1);
    hist_kernel<<<(NE + 255) / 256, 256, 0, s1>>>(edges);
    scan_kernel<<<1, 1024, 0, s1>>>();
    fill_kernel<<<(NE + 255) / 256, 256, 0, s1>>>(edges);
    cudaEventRecord(evCsr, s1);

    {
        int total = NN * HH + 376832;
        conv_kernel<<<(total + 255) / 256, 256>>>(x, msg_W, g0_Wih, g0_Whh,
                                                  g1_Wih, g1_Whh);
    }
    // CSR needed before first gather
    cudaStreamWaitEvent(0, evCsr, 0);

    const int GX = (NN + 127) / 128;   // 391
    for (int l = 0; l < 2; l++) {
        const __half* whh = pW16 + (l ? OFF_W1HH : OFF_W0HH);
        const float*  bhh = l ? g1_bhh : g0_bhh;
        const float*  bih = l ? g1_bih : g0_bih;
        const __half* mw  = pW16 + OFF_MSGW + (size_t)l * TT * HH * HH;
        for (int s = 0; s < 3; s++) {
            // msg GEMM (critical path) on main stream
            fusedh_kernel<<<dim3(GX, TT), 256, SMEM>>>(
                pH16, mw, whh, bhh, pM16, pGh16, 0);
            // fork gh GEMM onto s1 (off critical path)
            cudaEventRecord(evFork, 0);
            cudaStreamWaitEvent(s1, evFork, 0);
            fusedh_kernel<<<dim3(GX, 3), 256, SMEM, s1>>>(
                pH16, mw, whh, bhh, pM16, pGh16, TT);
            cudaEventRecord(evGh, s1);
            // gather + Wih on main stream, concurrent with gh
            gather_kernel<<<(NN * 32) / 256, 256>>>(msg_b + (size_t)l * TT * HH);
            if (l == 0)
                tgemm16_kernel<<<dim3(GX, 3), 256, SMEM>>>(
                    pInc16, nullptr, pW16 + OFF_W0IH, HH, bih, pGx16);
            else
                tgemm16_kernel<<<dim3(GX, 3), 256, SMEM>>>(
                    pX16, pInc16, pW16 + OFF_W1IH, 2 * HH, bih, pGx16);
            // join gh before gate
            cudaStreamWaitEvent(0, evGh, 0);
            bool last = (l == 1 && s == 2);
            gate_kernel<<<(NN * 32 + 255) / 256, 256>>>(pH, last ? (float*)d_out : pH);
        }
    }
}

// round 9
// speedup vs baseline: 5.3906x; 1.0284x over previous
#include <cuda_runtime.h>
#include <cuda_fp16.h>
#include <math.h>
#include <stdint.h>

#define NN 50000
#define HH 128
#define TT 4
#define EE 150000
#define NE (TT*EE)
#define G3H 384
#define TPAD 136   // halves per smem tile row

// ---------------- scratch (device globals; no allocation allowed) ----------
__device__ __half   g_M16[(size_t)TT*NN*HH];
__device__ __half   g_gx16[(size_t)NN*G3H];
__device__ __half   g_gh16[(size_t)NN*G3H];
__device__ float    g_h[(size_t)NN*HH];
__device__ __half   g_h16[(size_t)NN*HH];
__device__ __half   g_x16[(size_t)NN*HH];
__device__ __half   g_inc16[(size_t)NN*HH];
__device__ __half   g_w16[376832];
__device__ int      g_cnt[NN];
__device__ int      g_off[NN+1];
__device__ int      g_pos[NN];
__device__ unsigned g_ent[NE];

#define OFF_MSGW  0
#define OFF_W0IH  131072
#define OFF_W0HH  180224
#define OFF_W1IH  229376
#define OFF_W1HH  327680

__device__ __forceinline__ uint32_t smem_u32(const void* p) {
    uint32_t a;
    asm("{ .reg .u64 t; cvta.to.shared.u64 t, %1; cvt.u32.u64 %0, t; }" : "=r"(a) : "l"(p));
    return a;
}

#define LDSM_X4(r0, r1, r2, r3, addr) \
    asm volatile("ldmatrix.sync.aligned.m8n8.x4.shared.b16 {%0,%1,%2,%3}, [%4];" \
        : "=r"(r0), "=r"(r1), "=r"(r2), "=r"(r3) : "r"(addr))

// ---------------- fused prologue convert ----------------
__global__ void conv_kernel(const float* __restrict__ x,
                            const float* __restrict__ msgW,
                            const float* __restrict__ w0ih, const float* __restrict__ w0hh,
                            const float* __restrict__ w1ih, const float* __restrict__ w1hh)
{
    int i = blockIdx.x * blockDim.x + threadIdx.x;
    if (i < NN*HH) {
        float v = x[i];
        g_h[i] = v;
        __half hv = __float2half_rn(v);
        g_h16[i] = hv;
        g_x16[i] = hv;
    } else {
        int j = i - NN*HH;
        if (j < 131072)       g_w16[OFF_MSGW + j]            = __float2half_rn(msgW[j]);
        else if (j < 180224)  g_w16[OFF_W0IH + (j - 131072)] = __float2half_rn(w0ih[j - 131072]);
        else if (j < 229376)  g_w16[OFF_W0HH + (j - 180224)] = __float2half_rn(w0hh[j - 180224]);
        else if (j < 327680)  g_w16[OFF_W1IH + (j - 229376)] = __float2half_rn(w1ih[j - 229376]);
        else if (j < 376832)  g_w16[OFF_W1HH + (j - 327680)] = __float2half_rn(w1hh[j - 327680]);
    }
}

// ---------------- CSR build ----------------
__global__ void hist_kernel(const int* __restrict__ edges) {
    int i = blockIdx.x * blockDim.x + threadIdx.x;
    if (i < NE) atomicAdd(&g_cnt[edges[2*i+1]], 1);
}

__global__ void scan_kernel() {
    __shared__ int s[1024];
    __shared__ int carry;
    if (threadIdx.x == 0) carry = 0;
    __syncthreads();
    for (int base = 0; base < NN; base += 1024) {
        int i = base + threadIdx.x;
        int v = (i < NN) ? g_cnt[i] : 0;
        s[threadIdx.x] = v;
        __syncthreads();
        #pragma unroll
        for (int off = 1; off < 1024; off <<= 1) {
            int t = (threadIdx.x >= off) ? s[threadIdx.x - off] : 0;
            __syncthreads();
            s[threadIdx.x] += t;
            __syncthreads();
        }
        int excl = carry + s[threadIdx.x] - v;
        if (i < NN) { g_off[i] = excl; g_pos[i] = excl; }
        __syncthreads();
        if (threadIdx.x == 1023) carry += s[1023];
        __syncthreads();
    }
    if (threadIdx.x == 0) g_off[NN] = carry;
}

__global__ void fill_kernel(const int* __restrict__ edges) {
    int i = blockIdx.x * blockDim.x + threadIdx.x;
    if (i < NE) {
        int t   = i / EE;
        int src = edges[2*i];
        int tgt = edges[2*i+1];
        int p = atomicAdd(&g_pos[tgt], 1);
        g_ent[p] = ((unsigned)t << 16) | (unsigned)src;
    }
}

// ---------------- message gather ----------------
__global__ void gather_kernel(const float* __restrict__ b) {
    __shared__ float sb[TT*HH];
    for (int i = threadIdx.x; i < TT*HH; i += blockDim.x) sb[i] = b[i];
    __syncthreads();

    int gw   = (blockIdx.x * blockDim.x + threadIdx.x) >> 5;
    int lane = threadIdx.x & 31;
    if (gw >= NN) return;
    int s = g_off[gw], e = g_off[gw+1];
    float4 acc = make_float4(0.f, 0.f, 0.f, 0.f);

    int i = s;
    for (; i + 4 <= e; i += 4) {
        unsigned e0 = g_ent[i], e1 = g_ent[i+1], e2 = g_ent[i+2], e3 = g_ent[i+3];
        uint2 m0 = *(const uint2*)(g_M16 + ((size_t)(e0 >> 16)*NN + (e0 & 0xFFFFu))*HH + lane*4);
        uint2 m1 = *(const uint2*)(g_M16 + ((size_t)(e1 >> 16)*NN + (e1 & 0xFFFFu))*HH + lane*4);
        uint2 m2 = *(const uint2*)(g_M16 + ((size_t)(e2 >> 16)*NN + (e2 & 0xFFFFu))*HH + lane*4);
        uint2 m3 = *(const uint2*)(g_M16 + ((size_t)(e3 >> 16)*NN + (e3 & 0xFFFFu))*HH + lane*4);
        #pragma unroll
        for (int u = 0; u < 4; u++) {
            uint2 mv = (u == 0) ? m0 : (u == 1) ? m1 : (u == 2) ? m2 : m3;
            unsigned ent = (u == 0) ? e0 : (u == 1) ? e1 : (u == 2) ? e2 : e3;
            float2 a0 = __half22float2(*(__half2*)&mv.x);
            float2 a1 = __half22float2(*(__half2*)&mv.y);
            const float* bp = sb + (ent >> 16)*HH + lane*4;
            acc.x += a0.x + bp[0];
            acc.y += a0.y + bp[1];
            acc.z += a1.x + bp[2];
            acc.w += a1.y + bp[3];
        }
    }
    for (; i < e; i++) {
        unsigned ent = g_ent[i];
        uint2 mv = *(const uint2*)(g_M16 + ((size_t)(ent >> 16)*NN + (ent & 0xFFFFu))*HH + lane*4);
        float2 a0 = __half22float2(*(__half2*)&mv.x);
        float2 a1 = __half22float2(*(__half2*)&mv.y);
        const float* bp = sb + (ent >> 16)*HH + lane*4;
        acc.x += a0.x + bp[0];
        acc.y += a0.y + bp[1];
        acc.z += a1.x + bp[2];
        acc.w += a1.y + bp[3];
    }
    __half2 p0 = __floats2half2_rn(acc.x, acc.y);
    __half2 p1 = __floats2half2_rn(acc.z, acc.w);
    uint2 pk = make_uint2(*(uint32_t*)&p0, *(uint32_t*)&p1);
    *(uint2*)(g_inc16 + (size_t)gw*HH + lane*4) = pk;
}

// ======== shared GEMM mainloop pieces (ldmatrix + 2-stage K pipeline) ======
// stage half h (k columns [h*64, h*64+64)) of a 128-row tile
__device__ __forceinline__ void stage_half(const __half* __restrict__ A, int row_base,
                                           int row_limit, uint32_t sdst, int h, int tid,
                                           int ld) {
    #pragma unroll
    for (int it = 0; it < 4; it++) {
        int idx = tid + it * 256;
        int r = idx >> 3, c8 = (idx & 7) + h * 8;
        int gr = row_base + r;
        const __half* src = A + (size_t)(gr < row_limit ? gr : 0) * ld + c8 * 8;
        uint32_t dst = sdst + (r * TPAD + c8 * 8) * 2;
        int sz = (gr < row_limit) ? 16 : 0;
        asm volatile("cp.async.cg.shared.global [%0], [%1], 16, %2;"
                     :: "r"(dst), "l"(src), "r"(sz));
    }
}

// compute k-steps [ks0, ks0+4) with ldmatrix fragment loads
__device__ __forceinline__ void mma_half(const uint32_t* aAddr, const uint32_t* bAddr,
                                         int ks0, float acc[4][4][4]) {
    #pragma unroll
    for (int ks = ks0; ks < ks0 + 4; ks++) {
        uint32_t koff = (uint32_t)(ks * 32);   // 16 halves = 32 bytes per kstep
        uint32_t a[4][4], b[2][4];
        #pragma unroll
        for (int j2 = 0; j2 < 2; j2++)
            LDSM_X4(b[j2][0], b[j2][1], b[j2][2], b[j2][3], bAddr[j2] + koff);
        #pragma unroll
        for (int i = 0; i < 4; i++)
            LDSM_X4(a[i][0], a[i][1], a[i][2], a[i][3], aAddr[i] + koff);
        #pragma unroll
        for (int i = 0; i < 4; i++)
            #pragma unroll
            for (int j = 0; j < 4; j++) {
                const uint32_t* bf = &b[j >> 1][(j & 1) * 2];
                asm volatile(
                    "mma.sync.aligned.m16n8k16.row.col.f32.f16.f16.f32 "
                    "{%0,%1,%2,%3}, {%4,%5,%6,%7}, {%8,%9}, {%0,%1,%2,%3};"
                    : "+f"(acc[i][j][0]), "+f"(acc[i][j][1]),
                      "+f"(acc[i][j][2]), "+f"(acc[i][j][3])
                    : "r"(a[i][0]), "r"(a[i][1]), "r"(a[i][2]), "r"(a[i][3]),
                      "r"(bf[0]), "r"(bf[1]));
            }
    }
}

// precompute ldmatrix base addresses
__device__ __forceinline__ void ldsm_bases(uint32_t sAs, uint32_t sWs, int lane,
                                           int wm, int wn, uint32_t* aAddr, uint32_t* bAddr) {
    int t7 = lane & 7, sel = lane >> 3;
    #pragma unroll
    for (int i = 0; i < 4; i++)
        aAddr[i] = sAs + 2 * ((wm * 64 + i * 16 + (sel & 1) * 8 + t7) * TPAD + (sel >> 1) * 8);
    #pragma unroll
    for (int j2 = 0; j2 < 2; j2++)
        bAddr[j2] = sWs + 2 * ((wn * 32 + j2 * 16 + (sel >> 1) * 8 + t7) * TPAD + (sel & 1) * 8);
}

// ---------------- fused h-GEMM: per-type M (fp16) + gh (fp16) --------------
__global__ void __launch_bounds__(256, 2)
fusedh_kernel(const __half* __restrict__ A,
              const __half* __restrict__ msgW, const __half* __restrict__ whh,
              const float* __restrict__ bhh,
              __half* __restrict__ Mout, __half* __restrict__ ghout, int ybase)
{
    extern __shared__ __half smem[];
    __half* As = smem;
    __half* Ws = smem + 128 * TPAD;

    const int tid  = threadIdx.x;
    const int lane = tid & 31, warp = tid >> 5;
    const int wm = warp & 1, wn = warp >> 1;
    const int g  = lane >> 2, t4 = lane & 3;
    const int row_base = blockIdx.x * 128;
    const int yy = blockIdx.y + ybase;
    const bool is_msg = (yy < TT);
    const int cb = is_msg ? 0 : (yy - TT) * 128;
    const __half* W = is_msg ? (msgW + (size_t)yy * HH * HH)
                             : (whh + (size_t)cb * HH);

    const uint32_t sAs = smem_u32(As);
    const uint32_t sWs = smem_u32(Ws);
    uint32_t aAddr[4], bAddr[2];
    ldsm_bases(sAs, sWs, lane, wm, wn, aAddr, bAddr);

    float acc[4][4][4];
    #pragma unroll
    for (int i = 0; i < 4; i++)
        #pragma unroll
        for (int j = 0; j < 4; j++)
            #pragma unroll
            for (int q = 0; q < 4; q++) acc[i][j][q] = 0.f;

    // stage half0 then half1 as separate groups
    stage_half(A, row_base, NN, sAs, 0, tid, HH);
    stage_half(W, 0, 1 << 30, sWs, 0, tid, HH);
    asm volatile("cp.async.commit_group;");
    stage_half(A, row_base, NN, sAs, 1, tid, HH);
    stage_half(W, 0, 1 << 30, sWs, 1, tid, HH);
    asm volatile("cp.async.commit_group;");

    asm volatile("cp.async.wait_group 1;" ::: "memory");
    __syncthreads();
    mma_half(aAddr, bAddr, 0, acc);
    asm volatile("cp.async.wait_group 0;" ::: "memory");
    __syncthreads();
    mma_half(aAddr, bAddr, 4, acc);

    if (is_msg) {
        __half* C = Mout + (size_t)yy * NN * HH;
        #pragma unroll
        for (int i = 0; i < 4; i++) {
            int r0 = row_base + wm * 64 + i * 16 + g;
            #pragma unroll
            for (int j = 0; j < 4; j++) {
                int col = wn * 32 + j * 8 + 2 * t4;
                __half2 h0 = __floats2half2_rn(acc[i][j][0], acc[i][j][1]);
                __half2 h1 = __floats2half2_rn(acc[i][j][2], acc[i][j][3]);
                if (r0 < NN)
                    *(uint32_t*)(C + (size_t)r0 * HH + col) = *(uint32_t*)&h0;
                if (r0 + 8 < NN)
                    *(uint32_t*)(C + (size_t)(r0 + 8) * HH + col) = *(uint32_t*)&h1;
            }
        }
    } else {
        #pragma unroll
        for (int i = 0; i < 4; i++) {
            int r0 = row_base + wm * 64 + i * 16 + g;
            #pragma unroll
            for (int j = 0; j < 4; j++) {
                int col = cb + wn * 32 + j * 8 + 2 * t4;
                float b0 = bhh[col], b1 = bhh[col + 1];
                __half2 h0 = __floats2half2_rn(acc[i][j][0] + b0, acc[i][j][1] + b1);
                __half2 h1 = __floats2half2_rn(acc[i][j][2] + b0, acc[i][j][3] + b1);
                if (r0 < NN)
                    *(uint32_t*)(ghout + (size_t)r0 * G3H + col) = *(uint32_t*)&h0;
                if (r0 + 8 < NN)
                    *(uint32_t*)(ghout + (size_t)(r0 + 8) * G3H + col) = *(uint32_t*)&h1;
            }
        }
    }
}

// ---------------- Wih GEMM: gx = [A0|A1] @ Wih^T + bih (fp16 out) ----------
__global__ void __launch_bounds__(256, 2)
tgemm16_kernel(const __half* __restrict__ A0, const __half* __restrict__ A1,
               const __half* __restrict__ W, int ldW,
               const float* __restrict__ bias, __half* __restrict__ C)
{
    extern __shared__ __half smem[];
    __half* As = smem;
    __half* Ws = smem + 128 * TPAD;

    const int tid  = threadIdx.x;
    const int lane = tid & 31, warp = tid >> 5;
    const int wm = warp & 1, wn = warp >> 1;
    const int g  = lane >> 2, t4 = lane & 3;
    const int row_base = blockIdx.x * 128;
    const int cb = blockIdx.y * 128;

    const uint32_t sAs = smem_u32(As);
    const uint32_t sWs = smem_u32(Ws);
    uint32_t aAddr[4], bAddr[2];
    ldsm_bases(sAs, sWs, lane, wm, wn, aAddr, bAddr);

    float acc[4][4][4];
    #pragma unroll
    for (int i = 0; i < 4; i++)
        #pragma unroll
        for (int j = 0; j < 4; j++)
            #pragma unroll
            for (int q = 0; q < 4; q++) acc[i][j][q] = 0.f;

    const int nch = (A1 != nullptr) ? 2 : 1;
    for (int ch = 0; ch < nch; ch++) {
        const __half* A = ch ? A1 : A0;
        const __half* Wc = W + (size_t)cb * ldW + ch * 128;
        // stage W rows manually (ldW stride, offset cb) — reuse stage_half on
        // a shifted pointer with ld=ldW
        stage_half(A, row_base, NN, sAs, 0, tid, HH);
        stage_half(Wc, 0, 1 << 30, sWs, 0, tid, ldW);
        asm volatile("cp.async.commit_group;");
        stage_half(A, row_base, NN, sAs, 1, tid, HH);
        stage_half(Wc, 0, 1 << 30, sWs, 1, tid, ldW);
        asm volatile("cp.async.commit_group;");

        asm volatile("cp.async.wait_group 1;" ::: "memory");
        __syncthreads();
        mma_half(aAddr, bAddr, 0, acc);
        asm volatile("cp.async.wait_group 0;" ::: "memory");
        __syncthreads();
        mma_half(aAddr, bAddr, 4, acc);
        if (ch + 1 < nch) __syncthreads();
    }

    #pragma unroll
    for (int i = 0; i < 4; i++) {
        int r0 = row_base + wm * 64 + i * 16 + g;
        #pragma unroll
        for (int j = 0; j < 4; j++) {
            int col = cb + wn * 32 + j * 8 + 2 * t4;
            float b0 = bias[col], b1 = bias[col + 1];
            __half2 h0 = __floats2half2_rn(acc[i][j][0] + b0, acc[i][j][1] + b1);
            __half2 h1 = __floats2half2_rn(acc[i][j][2] + b0, acc[i][j][3] + b1);
            if (r0 < NN)
                *(uint32_t*)(C + (size_t)r0 * G3H + col) = *(uint32_t*)&h0;
            if (r0 + 8 < NN)
                *(uint32_t*)(C + (size_t)(r0 + 8) * G3H + col) = *(uint32_t*)&h1;
        }
    }
}

// ---------------- fused GRU gate: 4 features/thread ----------------
__global__ void gate_kernel(const float* __restrict__ h, float* __restrict__ hout) {
    int idx4 = blockIdx.x * blockDim.x + threadIdx.x;
    if (idx4 >= NN * 32) return;
    int n = idx4 >> 5, f4 = (idx4 & 31) * 4;
    const __half* gx = g_gx16 + (size_t)n * G3H + f4;
    const __half* gh = g_gh16 + (size_t)n * G3H + f4;
    uint2 uxr = *(const uint2*)gx;
    uint2 uxz = *(const uint2*)(gx + HH);
    uint2 uxn = *(const uint2*)(gx + 2 * HH);
    uint2 uhr = *(const uint2*)gh;
    uint2 uhz = *(const uint2*)(gh + HH);
    uint2 uhn = *(const uint2*)(gh + 2 * HH);
    float4 hv = *(const float4*)(h + (size_t)n * HH + f4);

    float o[4], hvv[4] = {hv.x, hv.y, hv.z, hv.w};
    #pragma unroll
    for (int u = 0; u < 2; u++) {
        float2 xr = __half22float2(*(__half2*)(&uxr.x + u));
        float2 xz = __half22float2(*(__half2*)(&uxz.x + u));
        float2 xn = __half22float2(*(__half2*)(&uxn.x + u));
        float2 hr = __half22float2(*(__half2*)(&uhr.x + u));
        float2 hz = __half22float2(*(__half2*)(&uhz.x + u));
        float2 hn = __half22float2(*(__half2*)(&uhn.x + u));
        float r0 = 1.f / (1.f + expf(-(xr.x + hr.x)));
        float r1 = 1.f / (1.f + expf(-(xr.y + hr.y)));
        float z0 = 1.f / (1.f + expf(-(xz.x + hz.x)));
        float z1 = 1.f / (1.f + expf(-(xz.y + hz.y)));
        float n0 = tanhf(xn.x + r0 * hn.x);
        float n1 = tanhf(xn.y + r1 * hn.y);
        o[2*u]   = (1.f - z0) * n0 + z0 * hvv[2*u];
        o[2*u+1] = (1.f - z1) * n1 + z1 * hvv[2*u+1];
    }

    *(float4*)(hout + (size_t)n * HH + f4) = make_float4(o[0], o[1], o[2], o[3]);
    __half2 oh0 = __floats2half2_rn(o[0], o[1]);
    __half2 oh1 = __floats2half2_rn(o[2], o[3]);
    uint2 pk = make_uint2(*(uint32_t*)&oh0, *(uint32_t*)&oh1);
    *(uint2*)(g_h16 + (size_t)n * HH + f4) = pk;
}

// ---------------- launch ----------------
extern "C" void kernel_launch(void* const* d_in, const int* in_sizes, int n_in,
                              void* d_out, int out_size) {
    const float* x      = (const float*)d_in[0];
    const int*   edges  = (const int*)  d_in[1];
    const float* msg_W  = (const float*)d_in[2];
    const float* msg_b  = (const float*)d_in[3];
    const float* g0_Wih = (const float*)d_in[4];
    const float* g0_Whh = (const float*)d_in[5];
    const float* g0_bih = (const float*)d_in[6];
    const float* g0_bhh = (const float*)d_in[7];
    const float* g1_Wih = (const float*)d_in[8];
    const float* g1_Whh = (const float*)d_in[9];
    const float* g1_bih = (const float*)d_in[10];
    const float* g1_bhh = (const float*)d_in[11];

    float *pH; int *pCnt;
    __half *pM16, *pH16, *pX16, *pInc16, *pW16, *pGx16, *pGh16;
    cudaGetSymbolAddress((void**)&pM16,  g_M16);
    cudaGetSymbolAddress((void**)&pGx16, g_gx16);
    cudaGetSymbolAddress((void**)&pGh16, g_gh16);
    cudaGetSymbolAddress((void**)&pH,    g_h);
    cudaGetSymbolAddress((void**)&pCnt,  g_cnt);
    cudaGetSymbolAddress((void**)&pH16,  g_h16);
    cudaGetSymbolAddress((void**)&pX16,  g_x16);
    cudaGetSymbolAddress((void**)&pInc16,g_inc16);
    cudaGetSymbolAddress((void**)&pW16,  g_w16);

    const int SMEM = 2 * 128 * TPAD * 2;   // 69632 B
    cudaFuncSetAttribute(fusedh_kernel,
                         cudaFuncAttributeMaxDynamicSharedMemorySize, SMEM);
    cudaFuncSetAttribute(tgemm16_kernel,
                         cudaFuncAttributeMaxDynamicSharedMemorySize, SMEM);

    static cudaStream_t s1 = nullptr;
    static cudaEvent_t evFork = nullptr, evGh = nullptr, evCsr = nullptr;
    if (s1 == nullptr) {
        cudaStreamCreateWithFlags(&s1, cudaStreamNonBlocking);
        cudaEventCreateWithFlags(&evFork, cudaEventDisableTiming);
        cudaEventCreateWithFlags(&evGh,   cudaEventDisableTiming);
        cudaEventCreateWithFlags(&evCsr,  cudaEventDisableTiming);
    }

    cudaEventRecord(evFork, 0);
    cudaStreamWaitEvent(s1, evFork, 0);
    cudaMemsetAsync(pCnt, 0, NN * sizeof(int), s1);
    hist_kernel<<<(NE + 255) / 256, 256, 0, s1>>>(edges);
    scan_kernel<<<1, 1024, 0, s1>>>();
    fill_kernel<<<(NE + 255) / 256, 256, 0, s1>>>(edges);
    cudaEventRecord(evCsr, s1);

    {
        int total = NN * HH + 376832;
        conv_kernel<<<(total + 255) / 256, 256>>>(x, msg_W, g0_Wih, g0_Whh,
                                                  g1_Wih, g1_Whh);
    }
    cudaStreamWaitEvent(0, evCsr, 0);

    const int GX = (NN + 127) / 128;   // 391
    for (int l = 0; l < 2; l++) {
        const __half* whh = pW16 + (l ? OFF_W1HH : OFF_W0HH);
        const float*  bhh = l ? g1_bhh : g0_bhh;
        const float*  bih = l ? g1_bih : g0_bih;
        const __half* mw  = pW16 + OFF_MSGW + (size_t)l * TT * HH * HH;
        for (int s = 0; s < 3; s++) {
            fusedh_kernel<<<dim3(GX, TT), 256, SMEM>>>(
                pH16, mw, whh, bhh, pM16, pGh16, 0);
            cudaEventRecord(evFork, 0);
            cudaStreamWaitEvent(s1, evFork, 0);
            fusedh_kernel<<<dim3(GX, 3), 256, SMEM, s1>>>(
                pH16, mw, whh, bhh, pM16, pGh16, TT);
            cudaEventRecord(evGh, s1);
            gather_kernel<<<(NN * 32) / 256, 256>>>(msg_b + (size_t)l * TT * HH);
            if (l == 0)
                tgemm16_kernel<<<dim3(GX, 3), 256, SMEM>>>(
                    pInc16, nullptr, pW16 + OFF_W0IH, HH, bih, pGx16);
            else
                tgemm16_kernel<<<dim3(GX, 3), 256, SMEM>>>(
                    pX16, pInc16, pW16 + OFF_W1IH, 2 * HH, bih, pGx16);
            cudaStreamWaitEvent(0, evGh, 0);
            bool last = (l == 1 && s == 2);
            gate_kernel<<<(NN * 32 + 255) / 256, 256>>>(pH, last ? (float*)d_out : pH);
        }
    }
}